// round 14
// baseline (speedup 1.0000x reference)
#include <cuda_runtime.h>
#include <cuda_bf16.h>
#include <math.h>
#include <stdint.h>

// Problem constants
#define S_LEN  2048
#define DMODEL 1024
#define NH     16
#define HD     64
#define BATCH  4
#define MROWS  (BATCH * S_LEN)   // 8192
#define N3     (3 * DMODEL)      // 3072

// Scratch (device globals; no allocation allowed)
__device__ __nv_bfloat16 g_ah[(size_t)MROWS * DMODEL];  // A hi (x, then ctx)
__device__ __nv_bfloat16 g_al[(size_t)MROWS * DMODEL];  // A lo
__device__ __nv_bfloat16 g_bh[(size_t)N3 * DMODEL];     // W hi (qkv_w, then o_w)
__device__ __nv_bfloat16 g_bl[(size_t)N3 * DMODEL];     // W lo
__device__ __nv_bfloat16 g_qh[(size_t)MROWS * N3];      // qkv hi (rope applied)
__device__ __nv_bfloat16 g_ql[(size_t)MROWS * N3];      // qkv lo
__device__ float2 g_rope[S_LEN * (HD / 2)];             // (cos, sin) packed

// ---------------------------------------------------------------------------
// PTX helpers (portable sm_80+ only)
// ---------------------------------------------------------------------------
__device__ __forceinline__ uint32_t smem_u32(const void* p) {
    uint32_t a;
    asm("{ .reg .u64 t; cvta.to.shared.u64 t, %1; cvt.u32.u64 %0, t; }" : "=r"(a) : "l"(p));
    return a;
}
__device__ __forceinline__ void cp_async16(uint32_t saddr, const void* gaddr) {
    asm volatile("cp.async.cg.shared.global [%0], [%1], 16;" :: "r"(saddr), "l"(gaddr));
}
__device__ __forceinline__ void ldsm_x4(uint32_t* r, uint32_t addr) {
    asm volatile("ldmatrix.sync.aligned.m8n8.x4.shared.b16 {%0,%1,%2,%3}, [%4];"
                 : "=r"(r[0]), "=r"(r[1]), "=r"(r[2]), "=r"(r[3]) : "r"(addr));
}
__device__ __forceinline__ void ldsm_x4_t(uint32_t* r, uint32_t addr) {
    asm volatile("ldmatrix.sync.aligned.m8n8.x4.trans.shared.b16 {%0,%1,%2,%3}, [%4];"
                 : "=r"(r[0]), "=r"(r[1]), "=r"(r[2]), "=r"(r[3]) : "r"(addr));
}
__device__ __forceinline__ void mma_bf16(float* c, const uint32_t* a, const uint32_t* b) {
    asm volatile(
        "mma.sync.aligned.m16n8k16.row.col.f32.bf16.bf16.f32 "
        "{%0,%1,%2,%3}, {%4,%5,%6,%7}, {%8,%9}, {%0,%1,%2,%3};"
        : "+f"(c[0]), "+f"(c[1]), "+f"(c[2]), "+f"(c[3])
        : "r"(a[0]), "r"(a[1]), "r"(a[2]), "r"(a[3]), "r"(b[0]), "r"(b[1]));
}
__device__ __forceinline__ uint32_t pack_bf16_res(float lo, float hi, float& rlo, float& rhi) {
    __nv_bfloat16 a = __float2bfloat16(lo), b = __float2bfloat16(hi);
    rlo = lo - __bfloat162float(a);
    rhi = hi - __bfloat162float(b);
    return (uint32_t)__bfloat16_as_ushort(a) | ((uint32_t)__bfloat16_as_ushort(b) << 16);
}
__device__ __forceinline__ uint32_t pack_bf16(float lo, float hi) {
    __nv_bfloat16 a = __float2bfloat16(lo), b = __float2bfloat16(hi);
    return (uint32_t)__bfloat16_as_ushort(a) | ((uint32_t)__bfloat16_as_ushort(b) << 16);
}

// ---------------------------------------------------------------------------
// fp32 -> bf16 hi/lo split
// ---------------------------------------------------------------------------
__global__ void split_bf16(const float* __restrict__ in,
                           __nv_bfloat16* __restrict__ hi,
                           __nv_bfloat16* __restrict__ lo, int n4) {
    int i = blockIdx.x * blockDim.x + threadIdx.x;
    if (i >= n4) return;
    float4 v = ((const float4*)in)[i];
    __nv_bfloat16 hx = __float2bfloat16(v.x), hy = __float2bfloat16(v.y);
    __nv_bfloat16 hz = __float2bfloat16(v.z), hw = __float2bfloat16(v.w);
    __nv_bfloat16 lx = __float2bfloat16(v.x - __bfloat162float(hx));
    __nv_bfloat16 ly = __float2bfloat16(v.y - __bfloat162float(hy));
    __nv_bfloat16 lz = __float2bfloat16(v.z - __bfloat162float(hz));
    __nv_bfloat16 lw = __float2bfloat16(v.w - __bfloat162float(hw));
    ((__nv_bfloat162*)hi)[i * 2]     = __nv_bfloat162(hx, hy);
    ((__nv_bfloat162*)hi)[i * 2 + 1] = __nv_bfloat162(hz, hw);
    ((__nv_bfloat162*)lo)[i * 2]     = __nv_bfloat162(lx, ly);
    ((__nv_bfloat162*)lo)[i * 2 + 1] = __nv_bfloat162(lz, lw);
}

// ---------------------------------------------------------------------------
// RoPE cos/sin table (same fp32 math as the proven rope kernel), float2-packed
// ---------------------------------------------------------------------------
__global__ void rope_tab(const int* __restrict__ pos, float2* __restrict__ tab) {
    int i = blockIdx.x * blockDim.x + threadIdx.x;
    if (i >= S_LEN * 32) return;
    int s = i >> 5, j = i & 31;
    float freq = powf(10000.0f, (float)j * (1.0f / 32.0f));
    float ang = (float)pos[s] * (1.0f / freq);
    float sn, cs;
    sincosf(ang, &sn, &cs);
    tab[i] = make_float2(cs, sn);
}

// ---------------------------------------------------------------------------
// Shared GEMM mainloop: mma.sync, swizzled smem, 3-stage cp.async pipeline,
// ONE barrier per chunk, warp-staggered (mf, ks) traversal.
// 128x128 CTA tile, 256 thr, K-chunk 32.
// ---------------------------------------------------------------------------
#define STAGE_BYTES 32768
#define GEMM_SMEM   (3 * STAGE_BYTES)
#define OFF_AH 0
#define OFF_AL 8192
#define OFF_BH 16384
#define OFF_BL 24576

__device__ __forceinline__ void load_stage(uint32_t sbase,
                                           const __nv_bfloat16* Ah, const __nv_bfloat16* Al,
                                           const __nv_bfloat16* Bh, const __nv_bfloat16* Bl,
                                           int K, int bm, int bn, int k0, int tid) {
#pragma unroll
    for (int i = 0; i < 2; i++) {
        int c = tid * 2 + i;
        int row = c >> 2;
        int cc = c & 3;
        uint32_t so = row * 64 + ((cc ^ ((row >> 1) & 3)) * 16);
        size_t goA = (size_t)(bm + row) * K + k0 + cc * 8;
        size_t goB = (size_t)(bn + row) * K + k0 + cc * 8;
        cp_async16(sbase + OFF_AH + so, Ah + goA);
        cp_async16(sbase + OFF_AL + so, Al + goA);
        cp_async16(sbase + OFF_BH + so, Bh + goB);
        cp_async16(sbase + OFF_BL + so, Bl + goB);
    }
}

__device__ __forceinline__ void gemm_mainloop(uint32_t sb,
                                              const __nv_bfloat16* Ah, const __nv_bfloat16* Al,
                                              const __nv_bfloat16* Bh, const __nv_bfloat16* Bl,
                                              int Kdim, int bm, int bn, int tid,
                                              float acc[4][4][4]) {
    const int wid = tid >> 5, lane = tid & 31;
    const int wm = wid >> 2, wn = wid & 3;
    const int a_row_base = wm * 64 + (lane & 15);
    const uint32_t axg = ((lane & 15) >> 1) & 3;
    const uint32_t a_csel = lane >> 4;
    const int b_row4 = wn * 32 + ((lane >> 4) & 1) * 8 + (lane & 7);
    const uint32_t b_kh = (lane >> 3) & 1;
    const int mfrot = wid & 3;          // stagger mf start per warp
    const int ksrot = (wid >> 2) & 1;   // flip ks order for half the warps

    const int nch = Kdim >> 5;
    load_stage(sb, Ah, Al, Bh, Bl, Kdim, bm, bn, 0, tid);
    asm volatile("cp.async.commit_group;");
    if (nch > 1) {
        load_stage(sb + STAGE_BYTES, Ah, Al, Bh, Bl, Kdim, bm, bn, 32, tid);
        asm volatile("cp.async.commit_group;");
    }

    int cur = 0, pre = 2;
    for (int c = 0; c < nch; c++) {
        if (c + 1 < nch) {
            asm volatile("cp.async.wait_group 1;");
        } else {
            asm volatile("cp.async.wait_group 0;");
        }
        __syncthreads();
        if (c + 2 < nch) {
            load_stage(sb + pre * STAGE_BYTES, Ah, Al, Bh, Bl,
                       Kdim, bm, bn, (c + 2) * 32, tid);
            asm volatile("cp.async.commit_group;");
            pre = (pre == 2) ? 0 : pre + 1;
        }

        const uint32_t st = sb + cur * STAGE_BYTES;
#pragma unroll
        for (int ks0 = 0; ks0 < 2; ks0++) {
            const int ks = ks0 ^ ksrot;
            uint32_t bh4[2][4], bl4[2][4];
#pragma unroll
            for (int np = 0; np < 2; np++) {
                int brow = b_row4 + np * 16;
                uint32_t bxg = ((uint32_t)brow >> 1) & 3;
                uint32_t baddr = st + brow * 64 + (((ks * 2 + b_kh) ^ bxg) * 16);
                ldsm_x4(bh4[np], baddr + OFF_BH);
                ldsm_x4(bl4[np], baddr + OFF_BL);
            }
#pragma unroll
            for (int mf0 = 0; mf0 < 4; mf0++) {
                const int mf = (mf0 + mfrot) & 3;
                uint32_t aaddr = st + (a_row_base + mf * 16) * 64 +
                                 (((ks * 2 + a_csel) ^ axg) * 16);
                uint32_t ah[4], al[4];
                ldsm_x4(ah, aaddr + OFF_AH);
                ldsm_x4(al, aaddr + OFF_AL);
#pragma unroll
                for (int np = 0; np < 2; np++)
#pragma unroll
                    for (int hf = 0; hf < 2; hf++)
                        mma_bf16(acc[mf][np * 2 + hf], ah, &bh4[np][hf * 2]);
#pragma unroll
                for (int np = 0; np < 2; np++)
#pragma unroll
                    for (int hf = 0; hf < 2; hf++)
                        mma_bf16(acc[mf][np * 2 + hf], ah, &bl4[np][hf * 2]);
#pragma unroll
                for (int np = 0; np < 2; np++)
#pragma unroll
                    for (int hf = 0; hf < 2; hf++)
                        mma_bf16(acc[mf][np * 2 + hf], al, &bh4[np][hf * 2]);
            }
        }
        cur = (cur == 2) ? 0 : cur + 1;
    }
    __syncthreads();   // protect smem before epilogue / next use
}

// ---------------------------------------------------------------------------
// QKV GEMM with fused RoPE + bf16 hi/lo output.
// ---------------------------------------------------------------------------
__global__ __launch_bounds__(256, 2) void gemm_qkv(const __nv_bfloat16* __restrict__ Ah,
                                                   const __nv_bfloat16* __restrict__ Al,
                                                   const __nv_bfloat16* __restrict__ Bh,
                                                   const __nv_bfloat16* __restrict__ Bl,
                                                   __nv_bfloat16* __restrict__ Qh,
                                                   __nv_bfloat16* __restrict__ Ql,
                                                   const float2* __restrict__ rtab) {
    extern __shared__ char smem[];
    const uint32_t sb = smem_u32(smem);
    const int tid = threadIdx.x;
    const int wid = tid >> 5, lane = tid & 31;
    const int bm = blockIdx.y * 128, bn = blockIdx.x * 128;

    float acc[4][4][4];
#pragma unroll
    for (int a = 0; a < 4; a++)
#pragma unroll
        for (int b = 0; b < 4; b++)
#pragma unroll
            for (int r = 0; r < 4; r++) acc[a][b][r] = 0.0f;

    gemm_mainloop(sb, Ah, Al, Bh, Bl, DMODEL, bm, bn, tid, acc);

    const int r0 = bm + (wid >> 2) * 64 + (lane >> 2);
    const int c0 = bn + (wid & 3) * 32 + (lane & 3) * 2;
#pragma unroll
    for (int mf = 0; mf < 4; mf++) {
        const int row = r0 + mf * 16;
        const int s0 = row & (S_LEN - 1);
        const int s1 = (row + 8) & (S_LEN - 1);
#pragma unroll
        for (int nf = 0; nf < 4; nf++) {
            const int col = c0 + nf * 8;
            float v0 = acc[mf][nf][0], v1 = acc[mf][nf][1];
            float v2 = acc[mf][nf][2], v3 = acc[mf][nf][3];
            if (col < 2 * DMODEL) {  // q or k: rotate
                const int j = (col & 63) >> 1;
                float2 t0v = rtab[s0 * 32 + j];
                float2 t1v = rtab[s1 * 32 + j];
                float t0 = v0 * t0v.x - v1 * t0v.y;
                v1 = v0 * t0v.y + v1 * t0v.x; v0 = t0;
                float t2 = v2 * t1v.x - v3 * t1v.y;
                v3 = v2 * t1v.y + v3 * t1v.x; v2 = t2;
            }
            float ra, rb;
            size_t i0 = (size_t)row * N3 + col;
            size_t i1 = (size_t)(row + 8) * N3 + col;
            uint32_t h0 = pack_bf16_res(v0, v1, ra, rb);
            *(uint32_t*)(Qh + i0) = h0;
            *(uint32_t*)(Ql + i0) = pack_bf16(ra, rb);
            uint32_t h1 = pack_bf16_res(v2, v3, ra, rb);
            *(uint32_t*)(Qh + i1) = h1;
            *(uint32_t*)(Ql + i1) = pack_bf16(ra, rb);
        }
    }
}

// ---------------------------------------------------------------------------
// O-projection GEMM: fp32 out.
// ---------------------------------------------------------------------------
__global__ __launch_bounds__(256, 2) void gemm_mma(const __nv_bfloat16* __restrict__ Ah,
                                                   const __nv_bfloat16* __restrict__ Al,
                                                   const __nv_bfloat16* __restrict__ Bh,
                                                   const __nv_bfloat16* __restrict__ Bl,
                                                   float* __restrict__ C,
                                                   int Ndim, int Kdim) {
    extern __shared__ char smem[];
    const uint32_t sb = smem_u32(smem);
    const int tid = threadIdx.x;
    const int wid = tid >> 5, lane = tid & 31;
    const int bm = blockIdx.y * 128, bn = blockIdx.x * 128;

    float acc[4][4][4];
#pragma unroll
    for (int a = 0; a < 4; a++)
#pragma unroll
        for (int b = 0; b < 4; b++)
#pragma unroll
            for (int r = 0; r < 4; r++) acc[a][b][r] = 0.0f;

    gemm_mainloop(sb, Ah, Al, Bh, Bl, Kdim, bm, bn, tid, acc);

    const int r0 = bm + (wid >> 2) * 64 + (lane >> 2);
    const int c0 = bn + (wid & 3) * 32 + (lane & 3) * 2;
#pragma unroll
    for (int mf = 0; mf < 4; mf++) {
#pragma unroll
        for (int nf = 0; nf < 4; nf++) {
            float* p0 = C + (size_t)(r0 + mf * 16) * Ndim + c0 + nf * 8;
            float* p1 = p0 + 8 * Ndim;
            *(float2*)p0 = make_float2(acc[mf][nf][0], acc[mf][nf][1]);
            *(float2*)p1 = make_float2(acc[mf][nf][2], acc[mf][nf][3]);
        }
    }
}

// ---------------------------------------------------------------------------
// Flash attention (mma.sync). CTA: 128 queries, 8 warps x 16 rows. KTILE 64.
// Double-buffered K/V, ONE barrier per tile, warp-staggered np traversal.
// smem 96KB: Q (32K) + 2 stages x (KH KL VH VL, 8K each).
// ---------------------------------------------------------------------------
#define AQH 0
#define AQL 16384
#define KVBASE 32768
#define KV_STAGE 32768
#define SKH 0
#define SKL 8192
#define SVH 16384
#define SVL 24576
#define ATT_SMEM 98304

__device__ __forceinline__ void attn_load_kv(uint32_t sbK, const __nv_bfloat16* Qh,
                                             const __nv_bfloat16* Ql, size_t mb,
                                             int kt, int koff, int voff, int tid) {
#pragma unroll
    for (int i = 0; i < 2; i++) {
        int c = tid + 256 * i;
        int row = c >> 3, j = c & 7;
        uint32_t dst = sbK + (uint32_t)(row * 128 + ((j ^ (row & 7)) * 16));
        size_t g = (mb + kt * 64 + row) * (size_t)N3 + j * 8;
        cp_async16(dst + SKH, Qh + g + koff);
        cp_async16(dst + SKL, Ql + g + koff);
        cp_async16(dst + SVH, Qh + g + voff);
        cp_async16(dst + SVL, Ql + g + voff);
    }
}

__global__ __launch_bounds__(256, 2) void attn_mma(const __nv_bfloat16* __restrict__ Qh,
                                                   const __nv_bfloat16* __restrict__ Ql,
                                                   __nv_bfloat16* __restrict__ Ch,
                                                   __nv_bfloat16* __restrict__ Cl) {
    extern __shared__ char smem[];
    const uint32_t sb = smem_u32(smem);
    const int qt = (S_LEN / 128 - 1) - blockIdx.x;   // big CTAs first
    const int bh = blockIdx.y;
    const int b = bh >> 4, h = bh & 15;
    const int tid = threadIdx.x;
    const int wq = tid >> 5, lane = tid & 31;
    const size_t mb = (size_t)b * S_LEN;
    const int qbase = qt * 128;
    const int qoff = h * HD;
    const int koff = DMODEL + h * HD;
    const int voff = 2 * DMODEL + h * HD;
    const uint32_t axor = (uint32_t)(lane & 7);
    const int nprot = wq & 3;   // stagger np start per warp

    // stage Q tile (128 rows x 64 cols, hi+lo)
#pragma unroll
    for (int i = 0; i < 4; i++) {
        int c = tid + 256 * i;
        int row = c >> 3, j = c & 7;
        uint32_t dst = sb + (uint32_t)(row * 128 + ((j ^ (row & 7)) * 16));
        size_t g = (mb + qbase + row) * (size_t)N3 + qoff + j * 8;
        cp_async16(dst + AQH, Qh + g);
        cp_async16(dst + AQL, Ql + g);
    }
    asm volatile("cp.async.commit_group;");
    // prefetch K/V tile 0
    attn_load_kv(sb + KVBASE, Qh, Ql, mb, 0, koff, voff, tid);
    asm volatile("cp.async.commit_group;");

    float o[8][4];
#pragma unroll
    for (int nf = 0; nf < 8; nf++)
#pragma unroll
        for (int r = 0; r < 4; r++) o[nf][r] = 0.0f;
    float m0 = -1e30f, m1 = -1e30f, l0 = 0.0f, l1 = 0.0f;

    const uint32_t qrow = wq * 16 + (lane & 15);
    const int grow0 = qbase + wq * 16 + (lane >> 2);
    const int colb = (lane & 3) * 2;
    const uint32_t k_row4 = ((lane >> 4) & 1) * 8 + (lane & 7);
    const uint32_t k_kh = (lane >> 3) & 1;

    const int nkt = 2 * (qt + 1);
    for (int kt = 0; kt < nkt; kt++) {
        asm volatile("cp.async.wait_group 0;");
        __syncthreads();
        if (kt + 1 < nkt) {
            attn_load_kv(sb + KVBASE + ((kt + 1) & 1) * KV_STAGE,
                         Qh, Ql, mb, kt + 1, koff, voff, tid);
            asm volatile("cp.async.commit_group;");
        }
        const uint32_t kb = sb + KVBASE + (kt & 1) * KV_STAGE;

        // ---- S = Q K^T (compensated, warp-staggered np) ----
        float s[8][4];
#pragma unroll
        for (int nf = 0; nf < 8; nf++)
#pragma unroll
            for (int r = 0; r < 4; r++) s[nf][r] = 0.0f;

#pragma unroll
        for (int ks = 0; ks < 4; ks++) {
            uint32_t qaddr = sb + qrow * 128 + (((2 * ks + (lane >> 4)) ^ axor) * 16);
            uint32_t qh4[4], ql4[4];
            ldsm_x4(qh4, qaddr + AQH);
            ldsm_x4(ql4, qaddr + AQL);
#pragma unroll
            for (int np0 = 0; np0 < 4; np0++) {
                const int np = (np0 + nprot) & 3;
                uint32_t krow = np * 16 + k_row4;
                uint32_t kaddr = kb + krow * 128 + (((2 * ks + k_kh) ^ axor) * 16);
                uint32_t kbh4[4], kbl4[4];
                ldsm_x4(kbh4, kaddr + SKH);
                ldsm_x4(kbl4, kaddr + SKL);
#pragma unroll
                for (int hf = 0; hf < 2; hf++)
                    mma_bf16(s[np * 2 + hf], qh4, &kbh4[hf * 2]);
#pragma unroll
                for (int hf = 0; hf < 2; hf++)
                    mma_bf16(s[np * 2 + hf], qh4, &kbl4[hf * 2]);
#pragma unroll
                for (int hf = 0; hf < 2; hf++)
                    mma_bf16(s[np * 2 + hf], ql4, &kbh4[hf * 2]);
            }
        }

        // ---- scale + causal mask + online softmax ----
        float mx0 = -1e30f, mx1 = -1e30f;
#pragma unroll
        for (int nf = 0; nf < 8; nf++) {
            int col = kt * 64 + nf * 8 + colb;
            float v0 = s[nf][0] * 0.125f;
            float v1 = s[nf][1] * 0.125f;
            float v2 = s[nf][2] * 0.125f;
            float v3 = s[nf][3] * 0.125f;
            if (col     > grow0)     v0 = -1e30f;
            if (col + 1 > grow0)     v1 = -1e30f;
            if (col     > grow0 + 8) v2 = -1e30f;
            if (col + 1 > grow0 + 8) v3 = -1e30f;
            s[nf][0] = v0; s[nf][1] = v1; s[nf][2] = v2; s[nf][3] = v3;
            mx0 = fmaxf(mx0, fmaxf(v0, v1));
            mx1 = fmaxf(mx1, fmaxf(v2, v3));
        }
        mx0 = fmaxf(mx0, __shfl_xor_sync(0xFFFFFFFFu, mx0, 1));
        mx0 = fmaxf(mx0, __shfl_xor_sync(0xFFFFFFFFu, mx0, 2));
        mx1 = fmaxf(mx1, __shfl_xor_sync(0xFFFFFFFFu, mx1, 1));
        mx1 = fmaxf(mx1, __shfl_xor_sync(0xFFFFFFFFu, mx1, 2));

        float mn0 = fmaxf(m0, mx0), mn1 = fmaxf(m1, mx1);
        float cr0 = __expf(m0 - mn0), cr1 = __expf(m1 - mn1);
        float rs0 = 0.0f, rs1 = 0.0f;
#pragma unroll
        for (int nf = 0; nf < 8; nf++) {
            s[nf][0] = __expf(s[nf][0] - mn0);
            s[nf][1] = __expf(s[nf][1] - mn0);
            s[nf][2] = __expf(s[nf][2] - mn1);
            s[nf][3] = __expf(s[nf][3] - mn1);
            rs0 += s[nf][0] + s[nf][1];
            rs1 += s[nf][2] + s[nf][3];
        }
        rs0 += __shfl_xor_sync(0xFFFFFFFFu, rs0, 1);
        rs0 += __shfl_xor_sync(0xFFFFFFFFu, rs0, 2);
        rs1 += __shfl_xor_sync(0xFFFFFFFFu, rs1, 1);
        rs1 += __shfl_xor_sync(0xFFFFFFFFu, rs1, 2);
        l0 = l0 * cr0 + rs0;
        l1 = l1 * cr1 + rs1;
        m0 = mn0; m1 = mn1;
#pragma unroll
        for (int nf = 0; nf < 8; nf++) {
            o[nf][0] *= cr0; o[nf][1] *= cr0;
            o[nf][2] *= cr1; o[nf][3] *= cr1;
        }

        // ---- O += P V (compensated, warp-staggered np) ----
#pragma unroll
        for (int ks = 0; ks < 4; ks++) {
            uint32_t pah[4], pal[4];
            float r0a, r0b, r1a, r1b;
            pah[0] = pack_bf16_res(s[2 * ks][0],     s[2 * ks][1],     r0a, r0b);
            pal[0] = pack_bf16(r0a, r0b);
            pah[1] = pack_bf16_res(s[2 * ks][2],     s[2 * ks][3],     r1a, r1b);
            pal[1] = pack_bf16(r1a, r1b);
            pah[2] = pack_bf16_res(s[2 * ks + 1][0], s[2 * ks + 1][1], r0a, r0b);
            pal[2] = pack_bf16(r0a, r0b);
            pah[3] = pack_bf16_res(s[2 * ks + 1][2], s[2 * ks + 1][3], r1a, r1b);
            pal[3] = pack_bf16(r1a, r1b);

            uint32_t vrow = ks * 16 + (lane & 15);
#pragma unroll
            for (int np0 = 0; np0 < 4; np0++) {
                const int np = (np0 + nprot) & 3;
                uint32_t vchunk = ((uint32_t)(2 * np) + (lane >> 4)) ^ axor;
                uint32_t vaddr = kb + vrow * 128 + (vchunk * 16);
                uint32_t vbh4[4], vbl4[4];
                ldsm_x4_t(vbh4, vaddr + SVH);
                ldsm_x4_t(vbl4, vaddr + SVL);
#pragma unroll
                for (int hf = 0; hf < 2; hf++)
                    mma_bf16(o[np * 2 + hf], pah, &vbh4[hf * 2]);
#pragma unroll
                for (int hf = 0; hf < 2; hf++)
                    mma_bf16(o[np * 2 + hf], pal, &vbh4[hf * 2]);
#pragma unroll
                for (int hf = 0; hf < 2; hf++)
                    mma_bf16(o[np * 2 + hf], pah, &vbl4[hf * 2]);
            }
        }
    }

    // epilogue: normalize, split hi/lo, write bf16 ctx (A of the O-projection)
    const float il0 = 1.0f / l0, il1 = 1.0f / l1;
    size_t i0 = (mb + qbase + wq * 16 + (lane >> 2)) * (size_t)DMODEL + h * HD + colb;
    size_t i1 = i0 + 8 * DMODEL;
#pragma unroll
    for (int nf = 0; nf < 8; nf++) {
        float ra, rb;
        uint32_t h0 = pack_bf16_res(o[nf][0] * il0, o[nf][1] * il0, ra, rb);
        *(uint32_t*)(Ch + i0 + nf * 8) = h0;
        *(uint32_t*)(Cl + i0 + nf * 8) = pack_bf16(ra, rb);
        uint32_t h1 = pack_bf16_res(o[nf][2] * il1, o[nf][3] * il1, ra, rb);
        *(uint32_t*)(Ch + i1 + nf * 8) = h1;
        *(uint32_t*)(Cl + i1 + nf * 8) = pack_bf16(ra, rb);
    }
}

// ---------------------------------------------------------------------------
// Launch
// ---------------------------------------------------------------------------
extern "C" void kernel_launch(void* const* d_in, const int* in_sizes, int n_in,
                              void* d_out, int out_size) {
    const float* x     = (const float*)d_in[0];   // [4,2048,1024]
    const int*   pos   = (const int*)d_in[1];     // [2048]
    const float* qkv_w = (const float*)d_in[2];   // [3072,1024]
    const float* o_w   = (const float*)d_in[3];   // [1024,1024]
    float* out = (float*)d_out;                   // [4,2048,1024]

    __nv_bfloat16 *ah, *al, *bh, *bl, *qh, *ql;
    float2* rt;
    cudaGetSymbolAddress((void**)&ah, g_ah);
    cudaGetSymbolAddress((void**)&al, g_al);
    cudaGetSymbolAddress((void**)&bh, g_bh);
    cudaGetSymbolAddress((void**)&bl, g_bl);
    cudaGetSymbolAddress((void**)&qh, g_qh);
    cudaGetSymbolAddress((void**)&ql, g_ql);
    cudaGetSymbolAddress((void**)&rt, g_rope);

    cudaFuncSetAttribute(gemm_qkv, cudaFuncAttributeMaxDynamicSharedMemorySize, GEMM_SMEM);
    cudaFuncSetAttribute(gemm_mma, cudaFuncAttributeMaxDynamicSharedMemorySize, GEMM_SMEM);
    cudaFuncSetAttribute(attn_mma, cudaFuncAttributeMaxDynamicSharedMemorySize, ATT_SMEM);

    // 1) splits + rope table
    {
        int n4 = MROWS * DMODEL / 4;
        split_bf16<<<(n4 + 255) / 256, 256>>>(x, ah, al, n4);
        n4 = N3 * DMODEL / 4;
        split_bf16<<<(n4 + 255) / 256, 256>>>(qkv_w, bh, bl, n4);
        rope_tab<<<(S_LEN * 32 + 255) / 256, 256>>>(pos, rt);
    }
    // 2) QKV projection + fused RoPE + bf16 split-out
    {
        dim3 grid(N3 / 128, MROWS / 128);
        gemm_qkv<<<grid, 256, GEMM_SMEM>>>(ah, al, bh, bl, qh, ql, rt);
    }
    // 3) flash attention -> ctx bf16 hi/lo (into ah/al)
    {
        dim3 grid(S_LEN / 128, BATCH * NH);
        attn_mma<<<grid, 256, ATT_SMEM>>>(qh, ql, ah, al);
    }
    // 4) split o_w
    {
        int n4 = DMODEL * DMODEL / 4;
        split_bf16<<<(n4 + 255) / 256, 256>>>(o_w, bh, bl, n4);
    }
    // 5) output projection -> fp32 out
    {
        dim3 grid(DMODEL / 128, MROWS / 128);
        gemm_mma<<<grid, 256, GEMM_SMEM>>>(ah, al, bh, bl, out, DMODEL, DMODEL);
    }
}

// round 15
// speedup vs baseline: 2.8178x; 2.8178x over previous
#include <cuda_runtime.h>
#include <cuda_bf16.h>
#include <math.h>
#include <stdint.h>

// Problem constants
#define S_LEN  2048
#define DMODEL 1024
#define NH     16
#define HD     64
#define BATCH  4
#define MROWS  (BATCH * S_LEN)   // 8192
#define N3     (3 * DMODEL)      // 3072

// Scratch (device globals; no allocation allowed)
__device__ __nv_bfloat16 g_ah[(size_t)MROWS * DMODEL];  // A hi (x, then ctx)
__device__ __nv_bfloat16 g_al[(size_t)MROWS * DMODEL];  // A lo
__device__ __nv_bfloat16 g_bh[(size_t)N3 * DMODEL];     // W hi (qkv_w, then o_w)
__device__ __nv_bfloat16 g_bl[(size_t)N3 * DMODEL];     // W lo
__device__ __nv_bfloat16 g_qh[(size_t)MROWS * N3];      // qkv hi (rope applied)
__device__ __nv_bfloat16 g_ql[(size_t)MROWS * N3];      // qkv lo
__device__ float2 g_rope[S_LEN * (HD / 2)];             // (cos, sin) packed

// ---------------------------------------------------------------------------
// PTX helpers (portable sm_80+ only)
// ---------------------------------------------------------------------------
__device__ __forceinline__ uint32_t smem_u32(const void* p) {
    uint32_t a;
    asm("{ .reg .u64 t; cvta.to.shared.u64 t, %1; cvt.u32.u64 %0, t; }" : "=r"(a) : "l"(p));
    return a;
}
__device__ __forceinline__ void cp_async16(uint32_t saddr, const void* gaddr) {
    asm volatile("cp.async.cg.shared.global [%0], [%1], 16;" :: "r"(saddr), "l"(gaddr));
}
__device__ __forceinline__ void ldsm_x4(uint32_t* r, uint32_t addr) {
    asm volatile("ldmatrix.sync.aligned.m8n8.x4.shared.b16 {%0,%1,%2,%3}, [%4];"
                 : "=r"(r[0]), "=r"(r[1]), "=r"(r[2]), "=r"(r[3]) : "r"(addr));
}
__device__ __forceinline__ void ldsm_x4_t(uint32_t* r, uint32_t addr) {
    asm volatile("ldmatrix.sync.aligned.m8n8.x4.trans.shared.b16 {%0,%1,%2,%3}, [%4];"
                 : "=r"(r[0]), "=r"(r[1]), "=r"(r[2]), "=r"(r[3]) : "r"(addr));
}
__device__ __forceinline__ void mma_bf16(float* c, const uint32_t* a, const uint32_t* b) {
    asm volatile(
        "mma.sync.aligned.m16n8k16.row.col.f32.bf16.bf16.f32 "
        "{%0,%1,%2,%3}, {%4,%5,%6,%7}, {%8,%9}, {%0,%1,%2,%3};"
        : "+f"(c[0]), "+f"(c[1]), "+f"(c[2]), "+f"(c[3])
        : "r"(a[0]), "r"(a[1]), "r"(a[2]), "r"(a[3]), "r"(b[0]), "r"(b[1]));
}
__device__ __forceinline__ uint32_t pack_bf16_res(float lo, float hi, float& rlo, float& rhi) {
    __nv_bfloat16 a = __float2bfloat16(lo), b = __float2bfloat16(hi);
    rlo = lo - __bfloat162float(a);
    rhi = hi - __bfloat162float(b);
    return (uint32_t)__bfloat16_as_ushort(a) | ((uint32_t)__bfloat16_as_ushort(b) << 16);
}
__device__ __forceinline__ uint32_t pack_bf16(float lo, float hi) {
    __nv_bfloat16 a = __float2bfloat16(lo), b = __float2bfloat16(hi);
    return (uint32_t)__bfloat16_as_ushort(a) | ((uint32_t)__bfloat16_as_ushort(b) << 16);
}

// ---------------------------------------------------------------------------
// fp32 -> bf16 hi/lo split (element helper)
// ---------------------------------------------------------------------------
__device__ __forceinline__ void split4(const float* __restrict__ in,
                                       __nv_bfloat16* __restrict__ hi,
                                       __nv_bfloat16* __restrict__ lo, int i) {
    float4 v = ((const float4*)in)[i];
    __nv_bfloat16 hx = __float2bfloat16(v.x), hy = __float2bfloat16(v.y);
    __nv_bfloat16 hz = __float2bfloat16(v.z), hw = __float2bfloat16(v.w);
    __nv_bfloat16 lx = __float2bfloat16(v.x - __bfloat162float(hx));
    __nv_bfloat16 ly = __float2bfloat16(v.y - __bfloat162float(hy));
    __nv_bfloat16 lz = __float2bfloat16(v.z - __bfloat162float(hz));
    __nv_bfloat16 lw = __float2bfloat16(v.w - __bfloat162float(hw));
    ((__nv_bfloat162*)hi)[i * 2]     = __nv_bfloat162(hx, hy);
    ((__nv_bfloat162*)hi)[i * 2 + 1] = __nv_bfloat162(hz, hw);
    ((__nv_bfloat162*)lo)[i * 2]     = __nv_bfloat162(lx, ly);
    ((__nv_bfloat162*)lo)[i * 2 + 1] = __nv_bfloat162(lz, lw);
}

__global__ void split_bf16(const float* __restrict__ in,
                           __nv_bfloat16* __restrict__ hi,
                           __nv_bfloat16* __restrict__ lo, int n4) {
    int i = blockIdx.x * blockDim.x + threadIdx.x;
    if (i >= n4) return;
    split4(in, hi, lo, i);
}

// ---------------------------------------------------------------------------
// Fused prep: split x, split qkv_w, build rope table — one launch.
// ---------------------------------------------------------------------------
#define NX4 (MROWS * DMODEL / 4)   // 2097152
#define NW4 (N3 * DMODEL / 4)      // 786432

__global__ void prep_all(const float* __restrict__ x,
                         const float* __restrict__ qkv_w,
                         const int* __restrict__ pos,
                         __nv_bfloat16* __restrict__ ah, __nv_bfloat16* __restrict__ al,
                         __nv_bfloat16* __restrict__ bh, __nv_bfloat16* __restrict__ bl,
                         float2* __restrict__ rtab) {
    int i = blockIdx.x * blockDim.x + threadIdx.x;
    if (i < NX4) {
        split4(x, ah, al, i);
    } else if (i < NX4 + NW4) {
        split4(qkv_w, bh, bl, i - NX4);
    } else {
        int j = i - NX4 - NW4;
        if (j < S_LEN * 32) {
            int s = j >> 5, k = j & 31;
            float freq = powf(10000.0f, (float)k * (1.0f / 32.0f));
            float ang = (float)pos[s] * (1.0f / freq);
            float sn, cs;
            sincosf(ang, &sn, &cs);
            rtab[j] = make_float2(cs, sn);
        }
    }
}

// ---------------------------------------------------------------------------
// Shared GEMM mainloop: mma.sync, swizzled smem, 3-stage cp.async pipeline.
// 128x128 CTA tile, 256 thr, K-chunk 32.  (round-12 schedule — proven best)
// ---------------------------------------------------------------------------
#define STAGE_BYTES 32768
#define GEMM_SMEM   (3 * STAGE_BYTES)
#define OFF_AH 0
#define OFF_AL 8192
#define OFF_BH 16384
#define OFF_BL 24576

__device__ __forceinline__ void load_stage(uint32_t sbase,
                                           const __nv_bfloat16* Ah, const __nv_bfloat16* Al,
                                           const __nv_bfloat16* Bh, const __nv_bfloat16* Bl,
                                           int K, int bm, int bn, int k0, int tid) {
#pragma unroll
    for (int i = 0; i < 2; i++) {
        int c = tid * 2 + i;
        int row = c >> 2;
        int cc = c & 3;
        uint32_t so = row * 64 + ((cc ^ ((row >> 1) & 3)) * 16);
        size_t goA = (size_t)(bm + row) * K + k0 + cc * 8;
        size_t goB = (size_t)(bn + row) * K + k0 + cc * 8;
        cp_async16(sbase + OFF_AH + so, Ah + goA);
        cp_async16(sbase + OFF_AL + so, Al + goA);
        cp_async16(sbase + OFF_BH + so, Bh + goB);
        cp_async16(sbase + OFF_BL + so, Bl + goB);
    }
}

__device__ __forceinline__ void gemm_mainloop(uint32_t sb,
                                              const __nv_bfloat16* Ah, const __nv_bfloat16* Al,
                                              const __nv_bfloat16* Bh, const __nv_bfloat16* Bl,
                                              int Kdim, int bm, int bn, int tid,
                                              float acc[4][4][4]) {
    const int wid = tid >> 5, lane = tid & 31;
    const int wm = wid >> 2, wn = wid & 3;
    const int a_row_base = wm * 64 + (lane & 15);
    const uint32_t axg = ((lane & 15) >> 1) & 3;
    const uint32_t a_csel = lane >> 4;
    const int b_row4 = wn * 32 + ((lane >> 4) & 1) * 8 + (lane & 7);
    const uint32_t b_kh = (lane >> 3) & 1;

    const int nch = Kdim >> 5;
    load_stage(sb, Ah, Al, Bh, Bl, Kdim, bm, bn, 0, tid);
    asm volatile("cp.async.commit_group;");
    if (nch > 1) {
        load_stage(sb + STAGE_BYTES, Ah, Al, Bh, Bl, Kdim, bm, bn, 32, tid);
        asm volatile("cp.async.commit_group;");
    }

    int cur = 0, pre = 2;
    for (int c = 0; c < nch; c++) {
        if (c + 2 < nch) {
            load_stage(sb + pre * STAGE_BYTES, Ah, Al, Bh, Bl,
                       Kdim, bm, bn, (c + 2) * 32, tid);
            asm volatile("cp.async.commit_group;");
            pre = (pre == 2) ? 0 : pre + 1;
            asm volatile("cp.async.wait_group 2;");
        } else if (c + 1 < nch) {
            asm volatile("cp.async.wait_group 1;");
        } else {
            asm volatile("cp.async.wait_group 0;");
        }
        __syncthreads();

        const uint32_t st = sb + cur * STAGE_BYTES;
#pragma unroll
        for (int ks = 0; ks < 2; ks++) {
            uint32_t bh4[2][4], bl4[2][4];
#pragma unroll
            for (int np = 0; np < 2; np++) {
                int brow = b_row4 + np * 16;
                uint32_t bxg = ((uint32_t)brow >> 1) & 3;
                uint32_t baddr = st + brow * 64 + (((ks * 2 + b_kh) ^ bxg) * 16);
                ldsm_x4(bh4[np], baddr + OFF_BH);
                ldsm_x4(bl4[np], baddr + OFF_BL);
            }
#pragma unroll
            for (int mf = 0; mf < 4; mf++) {
                uint32_t aaddr = st + (a_row_base + mf * 16) * 64 +
                                 (((ks * 2 + a_csel) ^ axg) * 16);
                uint32_t ah[4], al[4];
                ldsm_x4(ah, aaddr + OFF_AH);
                ldsm_x4(al, aaddr + OFF_AL);
#pragma unroll
                for (int np = 0; np < 2; np++)
#pragma unroll
                    for (int hf = 0; hf < 2; hf++)
                        mma_bf16(acc[mf][np * 2 + hf], ah, &bh4[np][hf * 2]);
#pragma unroll
                for (int np = 0; np < 2; np++)
#pragma unroll
                    for (int hf = 0; hf < 2; hf++)
                        mma_bf16(acc[mf][np * 2 + hf], ah, &bl4[np][hf * 2]);
#pragma unroll
                for (int np = 0; np < 2; np++)
#pragma unroll
                    for (int hf = 0; hf < 2; hf++)
                        mma_bf16(acc[mf][np * 2 + hf], al, &bh4[np][hf * 2]);
            }
        }
        cur = (cur == 2) ? 0 : cur + 1;
        __syncthreads();
    }
}

// ---------------------------------------------------------------------------
// QKV GEMM with fused RoPE + bf16 hi/lo output.
// ---------------------------------------------------------------------------
__global__ __launch_bounds__(256, 2) void gemm_qkv(const __nv_bfloat16* __restrict__ Ah,
                                                   const __nv_bfloat16* __restrict__ Al,
                                                   const __nv_bfloat16* __restrict__ Bh,
                                                   const __nv_bfloat16* __restrict__ Bl,
                                                   __nv_bfloat16* __restrict__ Qh,
                                                   __nv_bfloat16* __restrict__ Ql,
                                                   const float2* __restrict__ rtab) {
    extern __shared__ char smem[];
    const uint32_t sb = smem_u32(smem);
    const int tid = threadIdx.x;
    const int wid = tid >> 5, lane = tid & 31;
    const int bm = blockIdx.y * 128, bn = blockIdx.x * 128;

    float acc[4][4][4];
#pragma unroll
    for (int a = 0; a < 4; a++)
#pragma unroll
        for (int b = 0; b < 4; b++)
#pragma unroll
            for (int r = 0; r < 4; r++) acc[a][b][r] = 0.0f;

    gemm_mainloop(sb, Ah, Al, Bh, Bl, DMODEL, bm, bn, tid, acc);

    const int r0 = bm + (wid >> 2) * 64 + (lane >> 2);
    const int c0 = bn + (wid & 3) * 32 + (lane & 3) * 2;
#pragma unroll
    for (int mf = 0; mf < 4; mf++) {
        const int row = r0 + mf * 16;
        const int s0 = row & (S_LEN - 1);
        const int s1 = (row + 8) & (S_LEN - 1);
#pragma unroll
        for (int nf = 0; nf < 4; nf++) {
            const int col = c0 + nf * 8;
            float v0 = acc[mf][nf][0], v1 = acc[mf][nf][1];
            float v2 = acc[mf][nf][2], v3 = acc[mf][nf][3];
            if (col < 2 * DMODEL) {  // q or k: rotate
                const int j = (col & 63) >> 1;
                float2 t0v = rtab[s0 * 32 + j];
                float2 t1v = rtab[s1 * 32 + j];
                float t0 = v0 * t0v.x - v1 * t0v.y;
                v1 = v0 * t0v.y + v1 * t0v.x; v0 = t0;
                float t2 = v2 * t1v.x - v3 * t1v.y;
                v3 = v2 * t1v.y + v3 * t1v.x; v2 = t2;
            }
            float ra, rb;
            size_t i0 = (size_t)row * N3 + col;
            size_t i1 = (size_t)(row + 8) * N3 + col;
            uint32_t h0 = pack_bf16_res(v0, v1, ra, rb);
            *(uint32_t*)(Qh + i0) = h0;
            *(uint32_t*)(Ql + i0) = pack_bf16(ra, rb);
            uint32_t h1 = pack_bf16_res(v2, v3, ra, rb);
            *(uint32_t*)(Qh + i1) = h1;
            *(uint32_t*)(Ql + i1) = pack_bf16(ra, rb);
        }
    }
}

// ---------------------------------------------------------------------------
// O-projection GEMM: fp32 out.
// ---------------------------------------------------------------------------
__global__ __launch_bounds__(256, 2) void gemm_mma(const __nv_bfloat16* __restrict__ Ah,
                                                   const __nv_bfloat16* __restrict__ Al,
                                                   const __nv_bfloat16* __restrict__ Bh,
                                                   const __nv_bfloat16* __restrict__ Bl,
                                                   float* __restrict__ C,
                                                   int Ndim, int Kdim) {
    extern __shared__ char smem[];
    const uint32_t sb = smem_u32(smem);
    const int tid = threadIdx.x;
    const int wid = tid >> 5, lane = tid & 31;
    const int bm = blockIdx.y * 128, bn = blockIdx.x * 128;

    float acc[4][4][4];
#pragma unroll
    for (int a = 0; a < 4; a++)
#pragma unroll
        for (int b = 0; b < 4; b++)
#pragma unroll
            for (int r = 0; r < 4; r++) acc[a][b][r] = 0.0f;

    gemm_mainloop(sb, Ah, Al, Bh, Bl, Kdim, bm, bn, tid, acc);

    const int r0 = bm + (wid >> 2) * 64 + (lane >> 2);
    const int c0 = bn + (wid & 3) * 32 + (lane & 3) * 2;
#pragma unroll
    for (int mf = 0; mf < 4; mf++) {
#pragma unroll
        for (int nf = 0; nf < 4; nf++) {
            float* p0 = C + (size_t)(r0 + mf * 16) * Ndim + c0 + nf * 8;
            float* p1 = p0 + 8 * Ndim;
            *(float2*)p0 = make_float2(acc[mf][nf][0], acc[mf][nf][1]);
            *(float2*)p1 = make_float2(acc[mf][nf][2], acc[mf][nf][3]);
        }
    }
}

// ---------------------------------------------------------------------------
// Flash attention (mma.sync). CTA: 128 queries, 8 warps x 16 rows. KTILE 64.
// Double-buffered K/V (round-12 schedule — proven best).
// smem 96KB: Q (32K) + 2 stages x (KH KL VH VL, 8K each).
// ---------------------------------------------------------------------------
#define AQH 0
#define AQL 16384
#define KVBASE 32768
#define KV_STAGE 32768
#define SKH 0
#define SKL 8192
#define SVH 16384
#define SVL 24576
#define ATT_SMEM 98304

__device__ __forceinline__ void attn_load_kv(uint32_t sbK, const __nv_bfloat16* Qh,
                                             const __nv_bfloat16* Ql, size_t mb,
                                             int kt, int koff, int voff, int tid) {
#pragma unroll
    for (int i = 0; i < 2; i++) {
        int c = tid + 256 * i;
        int row = c >> 3, j = c & 7;
        uint32_t dst = sbK + (uint32_t)(row * 128 + ((j ^ (row & 7)) * 16));
        size_t g = (mb + kt * 64 + row) * (size_t)N3 + j * 8;
        cp_async16(dst + SKH, Qh + g + koff);
        cp_async16(dst + SKL, Ql + g + koff);
        cp_async16(dst + SVH, Qh + g + voff);
        cp_async16(dst + SVL, Ql + g + voff);
    }
}

__global__ __launch_bounds__(256, 2) void attn_mma(const __nv_bfloat16* __restrict__ Qh,
                                                   const __nv_bfloat16* __restrict__ Ql,
                                                   __nv_bfloat16* __restrict__ Ch,
                                                   __nv_bfloat16* __restrict__ Cl) {
    extern __shared__ char smem[];
    const uint32_t sb = smem_u32(smem);
    const int qt = (S_LEN / 128 - 1) - blockIdx.x;   // big CTAs first
    const int bh = blockIdx.y;
    const int b = bh >> 4, h = bh & 15;
    const int tid = threadIdx.x;
    const int wq = tid >> 5, lane = tid & 31;
    const size_t mb = (size_t)b * S_LEN;
    const int qbase = qt * 128;
    const int qoff = h * HD;
    const int koff = DMODEL + h * HD;
    const int voff = 2 * DMODEL + h * HD;
    const uint32_t axor = (uint32_t)(lane & 7);

    // stage Q tile (128 rows x 64 cols, hi+lo)
#pragma unroll
    for (int i = 0; i < 4; i++) {
        int c = tid + 256 * i;
        int row = c >> 3, j = c & 7;
        uint32_t dst = sb + (uint32_t)(row * 128 + ((j ^ (row & 7)) * 16));
        size_t g = (mb + qbase + row) * (size_t)N3 + qoff + j * 8;
        cp_async16(dst + AQH, Qh + g);
        cp_async16(dst + AQL, Ql + g);
    }
    asm volatile("cp.async.commit_group;");
    // prefetch K/V tile 0
    attn_load_kv(sb + KVBASE, Qh, Ql, mb, 0, koff, voff, tid);
    asm volatile("cp.async.commit_group;");

    float o[8][4];
#pragma unroll
    for (int nf = 0; nf < 8; nf++)
#pragma unroll
        for (int r = 0; r < 4; r++) o[nf][r] = 0.0f;
    float m0 = -1e30f, m1 = -1e30f, l0 = 0.0f, l1 = 0.0f;

    const uint32_t qrow = wq * 16 + (lane & 15);
    const int grow0 = qbase + wq * 16 + (lane >> 2);
    const int colb = (lane & 3) * 2;
    const uint32_t k_row4 = ((lane >> 4) & 1) * 8 + (lane & 7);
    const uint32_t k_kh = (lane >> 3) & 1;

    const int nkt = 2 * (qt + 1);
    for (int kt = 0; kt < nkt; kt++) {
        if (kt + 1 < nkt) {
            attn_load_kv(sb + KVBASE + ((kt + 1) & 1) * KV_STAGE,
                         Qh, Ql, mb, kt + 1, koff, voff, tid);
            asm volatile("cp.async.commit_group;");
            asm volatile("cp.async.wait_group 1;");
        } else {
            asm volatile("cp.async.wait_group 0;");
        }
        __syncthreads();
        const uint32_t kb = sb + KVBASE + (kt & 1) * KV_STAGE;

        // ---- S = Q K^T (compensated, term-major) ----
        float s[8][4];
#pragma unroll
        for (int nf = 0; nf < 8; nf++)
#pragma unroll
            for (int r = 0; r < 4; r++) s[nf][r] = 0.0f;

#pragma unroll
        for (int ks = 0; ks < 4; ks++) {
            uint32_t qaddr = sb + qrow * 128 + (((2 * ks + (lane >> 4)) ^ axor) * 16);
            uint32_t qh4[4], ql4[4];
            ldsm_x4(qh4, qaddr + AQH);
            ldsm_x4(ql4, qaddr + AQL);
#pragma unroll
            for (int np = 0; np < 4; np++) {
                uint32_t krow = np * 16 + k_row4;
                uint32_t kaddr = kb + krow * 128 + (((2 * ks + k_kh) ^ axor) * 16);
                uint32_t kbh4[4], kbl4[4];
                ldsm_x4(kbh4, kaddr + SKH);
                ldsm_x4(kbl4, kaddr + SKL);
#pragma unroll
                for (int hf = 0; hf < 2; hf++)
                    mma_bf16(s[np * 2 + hf], qh4, &kbh4[hf * 2]);
#pragma unroll
                for (int hf = 0; hf < 2; hf++)
                    mma_bf16(s[np * 2 + hf], qh4, &kbl4[hf * 2]);
#pragma unroll
                for (int hf = 0; hf < 2; hf++)
                    mma_bf16(s[np * 2 + hf], ql4, &kbh4[hf * 2]);
            }
        }

        // ---- scale + causal mask + online softmax ----
        float mx0 = -1e30f, mx1 = -1e30f;
#pragma unroll
        for (int nf = 0; nf < 8; nf++) {
            int col = kt * 64 + nf * 8 + colb;
            float v0 = s[nf][0] * 0.125f;
            float v1 = s[nf][1] * 0.125f;
            float v2 = s[nf][2] * 0.125f;
            float v3 = s[nf][3] * 0.125f;
            if (col     > grow0)     v0 = -1e30f;
            if (col + 1 > grow0)     v1 = -1e30f;
            if (col     > grow0 + 8) v2 = -1e30f;
            if (col + 1 > grow0 + 8) v3 = -1e30f;
            s[nf][0] = v0; s[nf][1] = v1; s[nf][2] = v2; s[nf][3] = v3;
            mx0 = fmaxf(mx0, fmaxf(v0, v1));
            mx1 = fmaxf(mx1, fmaxf(v2, v3));
        }
        mx0 = fmaxf(mx0, __shfl_xor_sync(0xFFFFFFFFu, mx0, 1));
        mx0 = fmaxf(mx0, __shfl_xor_sync(0xFFFFFFFFu, mx0, 2));
        mx1 = fmaxf(mx1, __shfl_xor_sync(0xFFFFFFFFu, mx1, 1));
        mx1 = fmaxf(mx1, __shfl_xor_sync(0xFFFFFFFFu, mx1, 2));

        float mn0 = fmaxf(m0, mx0), mn1 = fmaxf(m1, mx1);
        float cr0 = __expf(m0 - mn0), cr1 = __expf(m1 - mn1);
        float rs0 = 0.0f, rs1 = 0.0f;
#pragma unroll
        for (int nf = 0; nf < 8; nf++) {
            s[nf][0] = __expf(s[nf][0] - mn0);
            s[nf][1] = __expf(s[nf][1] - mn0);
            s[nf][2] = __expf(s[nf][2] - mn1);
            s[nf][3] = __expf(s[nf][3] - mn1);
            rs0 += s[nf][0] + s[nf][1];
            rs1 += s[nf][2] + s[nf][3];
        }
        rs0 += __shfl_xor_sync(0xFFFFFFFFu, rs0, 1);
        rs0 += __shfl_xor_sync(0xFFFFFFFFu, rs0, 2);
        rs1 += __shfl_xor_sync(0xFFFFFFFFu, rs1, 1);
        rs1 += __shfl_xor_sync(0xFFFFFFFFu, rs1, 2);
        l0 = l0 * cr0 + rs0;
        l1 = l1 * cr1 + rs1;
        m0 = mn0; m1 = mn1;
#pragma unroll
        for (int nf = 0; nf < 8; nf++) {
            o[nf][0] *= cr0; o[nf][1] *= cr0;
            o[nf][2] *= cr1; o[nf][3] *= cr1;
        }

        // ---- O += P V (compensated, term-major) ----
#pragma unroll
        for (int ks = 0; ks < 4; ks++) {
            uint32_t pah[4], pal[4];
            float r0a, r0b, r1a, r1b;
            pah[0] = pack_bf16_res(s[2 * ks][0],     s[2 * ks][1],     r0a, r0b);
            pal[0] = pack_bf16(r0a, r0b);
            pah[1] = pack_bf16_res(s[2 * ks][2],     s[2 * ks][3],     r1a, r1b);
            pal[1] = pack_bf16(r1a, r1b);
            pah[2] = pack_bf16_res(s[2 * ks + 1][0], s[2 * ks + 1][1], r0a, r0b);
            pal[2] = pack_bf16(r0a, r0b);
            pah[3] = pack_bf16_res(s[2 * ks + 1][2], s[2 * ks + 1][3], r1a, r1b);
            pal[3] = pack_bf16(r1a, r1b);

            uint32_t vrow = ks * 16 + (lane & 15);
#pragma unroll
            for (int np = 0; np < 4; np++) {
                uint32_t vchunk = ((uint32_t)(2 * np) + (lane >> 4)) ^ axor;
                uint32_t vaddr = kb + vrow * 128 + (vchunk * 16);
                uint32_t vbh4[4], vbl4[4];
                ldsm_x4_t(vbh4, vaddr + SVH);
                ldsm_x4_t(vbl4, vaddr + SVL);
#pragma unroll
                for (int hf = 0; hf < 2; hf++)
                    mma_bf16(o[np * 2 + hf], pah, &vbh4[hf * 2]);
#pragma unroll
                for (int hf = 0; hf < 2; hf++)
                    mma_bf16(o[np * 2 + hf], pal, &vbh4[hf * 2]);
#pragma unroll
                for (int hf = 0; hf < 2; hf++)
                    mma_bf16(o[np * 2 + hf], pah, &vbl4[hf * 2]);
            }
        }
        __syncthreads();
    }

    // epilogue: normalize, split hi/lo, write bf16 ctx (A of the O-projection)
    const float il0 = 1.0f / l0, il1 = 1.0f / l1;
    size_t i0 = (mb + qbase + wq * 16 + (lane >> 2)) * (size_t)DMODEL + h * HD + colb;
    size_t i1 = i0 + 8 * DMODEL;
#pragma unroll
    for (int nf = 0; nf < 8; nf++) {
        float ra, rb;
        uint32_t h0 = pack_bf16_res(o[nf][0] * il0, o[nf][1] * il0, ra, rb);
        *(uint32_t*)(Ch + i0 + nf * 8) = h0;
        *(uint32_t*)(Cl + i0 + nf * 8) = pack_bf16(ra, rb);
        uint32_t h1 = pack_bf16_res(o[nf][2] * il1, o[nf][3] * il1, ra, rb);
        *(uint32_t*)(Ch + i1 + nf * 8) = h1;
        *(uint32_t*)(Cl + i1 + nf * 8) = pack_bf16(ra, rb);
    }
}

// ---------------------------------------------------------------------------
// Launch
// ---------------------------------------------------------------------------
extern "C" void kernel_launch(void* const* d_in, const int* in_sizes, int n_in,
                              void* d_out, int out_size) {
    const float* x     = (const float*)d_in[0];   // [4,2048,1024]
    const int*   pos   = (const int*)d_in[1];     // [2048]
    const float* qkv_w = (const float*)d_in[2];   // [3072,1024]
    const float* o_w   = (const float*)d_in[3];   // [1024,1024]
    float* out = (float*)d_out;                   // [4,2048,1024]

    __nv_bfloat16 *ah, *al, *bh, *bl, *qh, *ql;
    float2* rt;
    cudaGetSymbolAddress((void**)&ah, g_ah);
    cudaGetSymbolAddress((void**)&al, g_al);
    cudaGetSymbolAddress((void**)&bh, g_bh);
    cudaGetSymbolAddress((void**)&bl, g_bl);
    cudaGetSymbolAddress((void**)&qh, g_qh);
    cudaGetSymbolAddress((void**)&ql, g_ql);
    cudaGetSymbolAddress((void**)&rt, g_rope);

    cudaFuncSetAttribute(gemm_qkv, cudaFuncAttributeMaxDynamicSharedMemorySize, GEMM_SMEM);
    cudaFuncSetAttribute(gemm_mma, cudaFuncAttributeMaxDynamicSharedMemorySize, GEMM_SMEM);
    cudaFuncSetAttribute(attn_mma, cudaFuncAttributeMaxDynamicSharedMemorySize, ATT_SMEM);

    // 1) fused prep: split x, split qkv_w, rope table (one launch)
    {
        int total = NX4 + NW4 + S_LEN * 32;
        prep_all<<<(total + 255) / 256, 256>>>(x, qkv_w, pos, ah, al, bh, bl, rt);
    }
    // 2) QKV projection + fused RoPE + bf16 split-out
    {
        dim3 grid(N3 / 128, MROWS / 128);
        gemm_qkv<<<grid, 256, GEMM_SMEM>>>(ah, al, bh, bl, qh, ql, rt);
    }
    // 3) flash attention -> ctx bf16 hi/lo (into ah/al)
    {
        dim3 grid(S_LEN / 128, BATCH * NH);
        attn_mma<<<grid, 256, ATT_SMEM>>>(qh, ql, ah, al);
    }
    // 4) split o_w
    {
        int n4 = DMODEL * DMODEL / 4;
        split_bf16<<<(n4 + 255) / 256, 256>>>(o_w, bh, bl, n4);
    }
    // 5) output projection -> fp32 out
    {
        dim3 grid(DMODEL / 128, MROWS / 128);
        gemm_mma<<<grid, 256, GEMM_SMEM>>>(ah, al, bh, bl, out, DMODEL, DMODEL);
    }
}

// round 16
// speedup vs baseline: 2.8265x; 1.0031x over previous
#include <cuda_runtime.h>
#include <cuda_bf16.h>
#include <math.h>
#include <stdint.h>

// Problem constants
#define S_LEN  2048
#define DMODEL 1024
#define NH     16
#define HD     64
#define BATCH  4
#define MROWS  (BATCH * S_LEN)   // 8192
#define N3     (3 * DMODEL)      // 3072

// Scratch (device globals; no allocation allowed)
__device__ __nv_bfloat16 g_ah[(size_t)MROWS * DMODEL];  // A hi (x, then ctx)
__device__ __nv_bfloat16 g_al[(size_t)MROWS * DMODEL];  // A lo
__device__ __nv_bfloat16 g_bh[(size_t)N3 * DMODEL];     // qkv_w hi
__device__ __nv_bfloat16 g_bl[(size_t)N3 * DMODEL];     // qkv_w lo
__device__ __nv_bfloat16 g_oh[(size_t)DMODEL * DMODEL]; // o_w hi
__device__ __nv_bfloat16 g_ol[(size_t)DMODEL * DMODEL]; // o_w lo
__device__ __nv_bfloat16 g_qh[(size_t)MROWS * N3];      // qkv hi (rope applied)
__device__ __nv_bfloat16 g_ql[(size_t)MROWS * N3];      // qkv lo
__device__ float2 g_rope[S_LEN * (HD / 2)];             // (cos, sin) packed

// ---------------------------------------------------------------------------
// PTX helpers (portable sm_80+ only)
// ---------------------------------------------------------------------------
__device__ __forceinline__ uint32_t smem_u32(const void* p) {
    uint32_t a;
    asm("{ .reg .u64 t; cvta.to.shared.u64 t, %1; cvt.u32.u64 %0, t; }" : "=r"(a) : "l"(p));
    return a;
}
__device__ __forceinline__ void cp_async16(uint32_t saddr, const void* gaddr) {
    asm volatile("cp.async.cg.shared.global [%0], [%1], 16;" :: "r"(saddr), "l"(gaddr));
}
__device__ __forceinline__ void ldsm_x4(uint32_t* r, uint32_t addr) {
    asm volatile("ldmatrix.sync.aligned.m8n8.x4.shared.b16 {%0,%1,%2,%3}, [%4];"
                 : "=r"(r[0]), "=r"(r[1]), "=r"(r[2]), "=r"(r[3]) : "r"(addr));
}
__device__ __forceinline__ void ldsm_x4_t(uint32_t* r, uint32_t addr) {
    asm volatile("ldmatrix.sync.aligned.m8n8.x4.trans.shared.b16 {%0,%1,%2,%3}, [%4];"
                 : "=r"(r[0]), "=r"(r[1]), "=r"(r[2]), "=r"(r[3]) : "r"(addr));
}
__device__ __forceinline__ void mma_bf16(float* c, const uint32_t* a, const uint32_t* b) {
    asm volatile(
        "mma.sync.aligned.m16n8k16.row.col.f32.bf16.bf16.f32 "
        "{%0,%1,%2,%3}, {%4,%5,%6,%7}, {%8,%9}, {%0,%1,%2,%3};"
        : "+f"(c[0]), "+f"(c[1]), "+f"(c[2]), "+f"(c[3])
        : "r"(a[0]), "r"(a[1]), "r"(a[2]), "r"(a[3]), "r"(b[0]), "r"(b[1]));
}
__device__ __forceinline__ uint32_t pack_bf16_res(float lo, float hi, float& rlo, float& rhi) {
    __nv_bfloat16 a = __float2bfloat16(lo), b = __float2bfloat16(hi);
    rlo = lo - __bfloat162float(a);
    rhi = hi - __bfloat162float(b);
    return (uint32_t)__bfloat16_as_ushort(a) | ((uint32_t)__bfloat16_as_ushort(b) << 16);
}
__device__ __forceinline__ uint32_t pack_bf16(float lo, float hi) {
    __nv_bfloat16 a = __float2bfloat16(lo), b = __float2bfloat16(hi);
    return (uint32_t)__bfloat16_as_ushort(a) | ((uint32_t)__bfloat16_as_ushort(b) << 16);
}

// ---------------------------------------------------------------------------
// fp32 -> bf16 hi/lo split (element helper)
// ---------------------------------------------------------------------------
__device__ __forceinline__ void split4(const float* __restrict__ in,
                                       __nv_bfloat16* __restrict__ hi,
                                       __nv_bfloat16* __restrict__ lo, int i) {
    float4 v = ((const float4*)in)[i];
    __nv_bfloat16 hx = __float2bfloat16(v.x), hy = __float2bfloat16(v.y);
    __nv_bfloat16 hz = __float2bfloat16(v.z), hw = __float2bfloat16(v.w);
    __nv_bfloat16 lx = __float2bfloat16(v.x - __bfloat162float(hx));
    __nv_bfloat16 ly = __float2bfloat16(v.y - __bfloat162float(hy));
    __nv_bfloat16 lz = __float2bfloat16(v.z - __bfloat162float(hz));
    __nv_bfloat16 lw = __float2bfloat16(v.w - __bfloat162float(hw));
    ((__nv_bfloat162*)hi)[i * 2]     = __nv_bfloat162(hx, hy);
    ((__nv_bfloat162*)hi)[i * 2 + 1] = __nv_bfloat162(hz, hw);
    ((__nv_bfloat162*)lo)[i * 2]     = __nv_bfloat162(lx, ly);
    ((__nv_bfloat162*)lo)[i * 2 + 1] = __nv_bfloat162(lz, lw);
}

// ---------------------------------------------------------------------------
// Fused prep: split x, split qkv_w, split o_w, build rope table — one launch.
// ---------------------------------------------------------------------------
#define NX4 (MROWS * DMODEL / 4)        // 2097152
#define NW4 (N3 * DMODEL / 4)           // 786432
#define NO4 (DMODEL * DMODEL / 4)       // 262144

__global__ void prep_all(const float* __restrict__ x,
                         const float* __restrict__ qkv_w,
                         const float* __restrict__ o_w,
                         const int* __restrict__ pos,
                         __nv_bfloat16* __restrict__ ah, __nv_bfloat16* __restrict__ al,
                         __nv_bfloat16* __restrict__ bh, __nv_bfloat16* __restrict__ bl,
                         __nv_bfloat16* __restrict__ oh, __nv_bfloat16* __restrict__ ol,
                         float2* __restrict__ rtab) {
    int i = blockIdx.x * blockDim.x + threadIdx.x;
    if (i < NX4) {
        split4(x, ah, al, i);
    } else if (i < NX4 + NW4) {
        split4(qkv_w, bh, bl, i - NX4);
    } else if (i < NX4 + NW4 + NO4) {
        split4(o_w, oh, ol, i - NX4 - NW4);
    } else {
        int j = i - NX4 - NW4 - NO4;
        if (j < S_LEN * 32) {
            int s = j >> 5, k = j & 31;
            float freq = powf(10000.0f, (float)k * (1.0f / 32.0f));
            float ang = (float)pos[s] * (1.0f / freq);
            float sn, cs;
            sincosf(ang, &sn, &cs);
            rtab[j] = make_float2(cs, sn);
        }
    }
}

// ---------------------------------------------------------------------------
// Shared GEMM mainloop: mma.sync, swizzled smem, 3-stage cp.async pipeline.
// 128x128 CTA tile, 256 thr, K-chunk 32.  (round-12 schedule — proven best)
// ---------------------------------------------------------------------------
#define STAGE_BYTES 32768
#define GEMM_SMEM   (3 * STAGE_BYTES)
#define OFF_AH 0
#define OFF_AL 8192
#define OFF_BH 16384
#define OFF_BL 24576

__device__ __forceinline__ void load_stage(uint32_t sbase,
                                           const __nv_bfloat16* Ah, const __nv_bfloat16* Al,
                                           const __nv_bfloat16* Bh, const __nv_bfloat16* Bl,
                                           int K, int bm, int bn, int k0, int tid) {
#pragma unroll
    for (int i = 0; i < 2; i++) {
        int c = tid * 2 + i;
        int row = c >> 2;
        int cc = c & 3;
        uint32_t so = row * 64 + ((cc ^ ((row >> 1) & 3)) * 16);
        size_t goA = (size_t)(bm + row) * K + k0 + cc * 8;
        size_t goB = (size_t)(bn + row) * K + k0 + cc * 8;
        cp_async16(sbase + OFF_AH + so, Ah + goA);
        cp_async16(sbase + OFF_AL + so, Al + goA);
        cp_async16(sbase + OFF_BH + so, Bh + goB);
        cp_async16(sbase + OFF_BL + so, Bl + goB);
    }
}

__device__ __forceinline__ void gemm_mainloop(uint32_t sb,
                                              const __nv_bfloat16* Ah, const __nv_bfloat16* Al,
                                              const __nv_bfloat16* Bh, const __nv_bfloat16* Bl,
                                              int Kdim, int bm, int bn, int tid,
                                              float acc[4][4][4]) {
    const int wid = tid >> 5, lane = tid & 31;
    const int wm = wid >> 2, wn = wid & 3;
    const int a_row_base = wm * 64 + (lane & 15);
    const uint32_t axg = ((lane & 15) >> 1) & 3;
    const uint32_t a_csel = lane >> 4;
    const int b_row4 = wn * 32 + ((lane >> 4) & 1) * 8 + (lane & 7);
    const uint32_t b_kh = (lane >> 3) & 1;

    const int nch = Kdim >> 5;
    load_stage(sb, Ah, Al, Bh, Bl, Kdim, bm, bn, 0, tid);
    asm volatile("cp.async.commit_group;");
    if (nch > 1) {
        load_stage(sb + STAGE_BYTES, Ah, Al, Bh, Bl, Kdim, bm, bn, 32, tid);
        asm volatile("cp.async.commit_group;");
    }

    int cur = 0, pre = 2;
    for (int c = 0; c < nch; c++) {
        if (c + 2 < nch) {
            load_stage(sb + pre * STAGE_BYTES, Ah, Al, Bh, Bl,
                       Kdim, bm, bn, (c + 2) * 32, tid);
            asm volatile("cp.async.commit_group;");
            pre = (pre == 2) ? 0 : pre + 1;
            asm volatile("cp.async.wait_group 2;");
        } else if (c + 1 < nch) {
            asm volatile("cp.async.wait_group 1;");
        } else {
            asm volatile("cp.async.wait_group 0;");
        }
        __syncthreads();

        const uint32_t st = sb + cur * STAGE_BYTES;
#pragma unroll
        for (int ks = 0; ks < 2; ks++) {
            uint32_t bh4[2][4], bl4[2][4];
#pragma unroll
            for (int np = 0; np < 2; np++) {
                int brow = b_row4 + np * 16;
                uint32_t bxg = ((uint32_t)brow >> 1) & 3;
                uint32_t baddr = st + brow * 64 + (((ks * 2 + b_kh) ^ bxg) * 16);
                ldsm_x4(bh4[np], baddr + OFF_BH);
                ldsm_x4(bl4[np], baddr + OFF_BL);
            }
#pragma unroll
            for (int mf = 0; mf < 4; mf++) {
                uint32_t aaddr = st + (a_row_base + mf * 16) * 64 +
                                 (((ks * 2 + a_csel) ^ axg) * 16);
                uint32_t ah[4], al[4];
                ldsm_x4(ah, aaddr + OFF_AH);
                ldsm_x4(al, aaddr + OFF_AL);
#pragma unroll
                for (int np = 0; np < 2; np++)
#pragma unroll
                    for (int hf = 0; hf < 2; hf++)
                        mma_bf16(acc[mf][np * 2 + hf], ah, &bh4[np][hf * 2]);
#pragma unroll
                for (int np = 0; np < 2; np++)
#pragma unroll
                    for (int hf = 0; hf < 2; hf++)
                        mma_bf16(acc[mf][np * 2 + hf], ah, &bl4[np][hf * 2]);
#pragma unroll
                for (int np = 0; np < 2; np++)
#pragma unroll
                    for (int hf = 0; hf < 2; hf++)
                        mma_bf16(acc[mf][np * 2 + hf], al, &bh4[np][hf * 2]);
            }
        }
        cur = (cur == 2) ? 0 : cur + 1;
        __syncthreads();
    }
}

// ---------------------------------------------------------------------------
// QKV GEMM with fused RoPE + bf16 hi/lo output.
// ---------------------------------------------------------------------------
__global__ __launch_bounds__(256, 2) void gemm_qkv(const __nv_bfloat16* __restrict__ Ah,
                                                   const __nv_bfloat16* __restrict__ Al,
                                                   const __nv_bfloat16* __restrict__ Bh,
                                                   const __nv_bfloat16* __restrict__ Bl,
                                                   __nv_bfloat16* __restrict__ Qh,
                                                   __nv_bfloat16* __restrict__ Ql,
                                                   const float2* __restrict__ rtab) {
    extern __shared__ char smem[];
    const uint32_t sb = smem_u32(smem);
    const int tid = threadIdx.x;
    const int wid = tid >> 5, lane = tid & 31;
    const int bm = blockIdx.y * 128, bn = blockIdx.x * 128;

    float acc[4][4][4];
#pragma unroll
    for (int a = 0; a < 4; a++)
#pragma unroll
        for (int b = 0; b < 4; b++)
#pragma unroll
            for (int r = 0; r < 4; r++) acc[a][b][r] = 0.0f;

    gemm_mainloop(sb, Ah, Al, Bh, Bl, DMODEL, bm, bn, tid, acc);

    const int r0 = bm + (wid >> 2) * 64 + (lane >> 2);
    const int c0 = bn + (wid & 3) * 32 + (lane & 3) * 2;
#pragma unroll
    for (int mf = 0; mf < 4; mf++) {
        const int row = r0 + mf * 16;
        const int s0 = row & (S_LEN - 1);
        const int s1 = (row + 8) & (S_LEN - 1);
#pragma unroll
        for (int nf = 0; nf < 4; nf++) {
            const int col = c0 + nf * 8;
            float v0 = acc[mf][nf][0], v1 = acc[mf][nf][1];
            float v2 = acc[mf][nf][2], v3 = acc[mf][nf][3];
            if (col < 2 * DMODEL) {  // q or k: rotate
                const int j = (col & 63) >> 1;
                float2 t0v = rtab[s0 * 32 + j];
                float2 t1v = rtab[s1 * 32 + j];
                float t0 = v0 * t0v.x - v1 * t0v.y;
                v1 = v0 * t0v.y + v1 * t0v.x; v0 = t0;
                float t2 = v2 * t1v.x - v3 * t1v.y;
                v3 = v2 * t1v.y + v3 * t1v.x; v2 = t2;
            }
            float ra, rb;
            size_t i0 = (size_t)row * N3 + col;
            size_t i1 = (size_t)(row + 8) * N3 + col;
            uint32_t h0 = pack_bf16_res(v0, v1, ra, rb);
            *(uint32_t*)(Qh + i0) = h0;
            *(uint32_t*)(Ql + i0) = pack_bf16(ra, rb);
            uint32_t h1 = pack_bf16_res(v2, v3, ra, rb);
            *(uint32_t*)(Qh + i1) = h1;
            *(uint32_t*)(Ql + i1) = pack_bf16(ra, rb);
        }
    }
}

// ---------------------------------------------------------------------------
// O-projection GEMM: fp32 out.
// ---------------------------------------------------------------------------
__global__ __launch_bounds__(256, 2) void gemm_mma(const __nv_bfloat16* __restrict__ Ah,
                                                   const __nv_bfloat16* __restrict__ Al,
                                                   const __nv_bfloat16* __restrict__ Bh,
                                                   const __nv_bfloat16* __restrict__ Bl,
                                                   float* __restrict__ C,
                                                   int Ndim, int Kdim) {
    extern __shared__ char smem[];
    const uint32_t sb = smem_u32(smem);
    const int tid = threadIdx.x;
    const int wid = tid >> 5, lane = tid & 31;
    const int bm = blockIdx.y * 128, bn = blockIdx.x * 128;

    float acc[4][4][4];
#pragma unroll
    for (int a = 0; a < 4; a++)
#pragma unroll
        for (int b = 0; b < 4; b++)
#pragma unroll
            for (int r = 0; r < 4; r++) acc[a][b][r] = 0.0f;

    gemm_mainloop(sb, Ah, Al, Bh, Bl, Kdim, bm, bn, tid, acc);

    const int r0 = bm + (wid >> 2) * 64 + (lane >> 2);
    const int c0 = bn + (wid & 3) * 32 + (lane & 3) * 2;
#pragma unroll
    for (int mf = 0; mf < 4; mf++) {
#pragma unroll
        for (int nf = 0; nf < 4; nf++) {
            float* p0 = C + (size_t)(r0 + mf * 16) * Ndim + c0 + nf * 8;
            float* p1 = p0 + 8 * Ndim;
            *(float2*)p0 = make_float2(acc[mf][nf][0], acc[mf][nf][1]);
            *(float2*)p1 = make_float2(acc[mf][nf][2], acc[mf][nf][3]);
        }
    }
}

// ---------------------------------------------------------------------------
// Flash attention (mma.sync). CTA: 128 queries, 8 warps x 16 rows. KTILE 64.
// Double-buffered K/V (round-12 schedule — proven best).
// smem 96KB: Q (32K) + 2 stages x (KH KL VH VL, 8K each).
// ---------------------------------------------------------------------------
#define AQH 0
#define AQL 16384
#define KVBASE 32768
#define KV_STAGE 32768
#define SKH 0
#define SKL 8192
#define SVH 16384
#define SVL 24576
#define ATT_SMEM 98304

__device__ __forceinline__ void attn_load_kv(uint32_t sbK, const __nv_bfloat16* Qh,
                                             const __nv_bfloat16* Ql, size_t mb,
                                             int kt, int koff, int voff, int tid) {
#pragma unroll
    for (int i = 0; i < 2; i++) {
        int c = tid + 256 * i;
        int row = c >> 3, j = c & 7;
        uint32_t dst = sbK + (uint32_t)(row * 128 + ((j ^ (row & 7)) * 16));
        size_t g = (mb + kt * 64 + row) * (size_t)N3 + j * 8;
        cp_async16(dst + SKH, Qh + g + koff);
        cp_async16(dst + SKL, Ql + g + koff);
        cp_async16(dst + SVH, Qh + g + voff);
        cp_async16(dst + SVL, Ql + g + voff);
    }
}

__global__ __launch_bounds__(256, 2) void attn_mma(const __nv_bfloat16* __restrict__ Qh,
                                                   const __nv_bfloat16* __restrict__ Ql,
                                                   __nv_bfloat16* __restrict__ Ch,
                                                   __nv_bfloat16* __restrict__ Cl) {
    extern __shared__ char smem[];
    const uint32_t sb = smem_u32(smem);
    const int qt = (S_LEN / 128 - 1) - blockIdx.x;   // big CTAs first
    const int bh = blockIdx.y;
    const int b = bh >> 4, h = bh & 15;
    const int tid = threadIdx.x;
    const int wq = tid >> 5, lane = tid & 31;
    const size_t mb = (size_t)b * S_LEN;
    const int qbase = qt * 128;
    const int qoff = h * HD;
    const int koff = DMODEL + h * HD;
    const int voff = 2 * DMODEL + h * HD;
    const uint32_t axor = (uint32_t)(lane & 7);

    // stage Q tile (128 rows x 64 cols, hi+lo)
#pragma unroll
    for (int i = 0; i < 4; i++) {
        int c = tid + 256 * i;
        int row = c >> 3, j = c & 7;
        uint32_t dst = sb + (uint32_t)(row * 128 + ((j ^ (row & 7)) * 16));
        size_t g = (mb + qbase + row) * (size_t)N3 + qoff + j * 8;
        cp_async16(dst + AQH, Qh + g);
        cp_async16(dst + AQL, Ql + g);
    }
    asm volatile("cp.async.commit_group;");
    // prefetch K/V tile 0
    attn_load_kv(sb + KVBASE, Qh, Ql, mb, 0, koff, voff, tid);
    asm volatile("cp.async.commit_group;");

    float o[8][4];
#pragma unroll
    for (int nf = 0; nf < 8; nf++)
#pragma unroll
        for (int r = 0; r < 4; r++) o[nf][r] = 0.0f;
    float m0 = -1e30f, m1 = -1e30f, l0 = 0.0f, l1 = 0.0f;

    const uint32_t qrow = wq * 16 + (lane & 15);
    const int grow0 = qbase + wq * 16 + (lane >> 2);
    const int colb = (lane & 3) * 2;
    const uint32_t k_row4 = ((lane >> 4) & 1) * 8 + (lane & 7);
    const uint32_t k_kh = (lane >> 3) & 1;

    const int nkt = 2 * (qt + 1);
    for (int kt = 0; kt < nkt; kt++) {
        if (kt + 1 < nkt) {
            attn_load_kv(sb + KVBASE + ((kt + 1) & 1) * KV_STAGE,
                         Qh, Ql, mb, kt + 1, koff, voff, tid);
            asm volatile("cp.async.commit_group;");
            asm volatile("cp.async.wait_group 1;");
        } else {
            asm volatile("cp.async.wait_group 0;");
        }
        __syncthreads();
        const uint32_t kb = sb + KVBASE + (kt & 1) * KV_STAGE;

        // ---- S = Q K^T (compensated, term-major) ----
        float s[8][4];
#pragma unroll
        for (int nf = 0; nf < 8; nf++)
#pragma unroll
            for (int r = 0; r < 4; r++) s[nf][r] = 0.0f;

#pragma unroll
        for (int ks = 0; ks < 4; ks++) {
            uint32_t qaddr = sb + qrow * 128 + (((2 * ks + (lane >> 4)) ^ axor) * 16);
            uint32_t qh4[4], ql4[4];
            ldsm_x4(qh4, qaddr + AQH);
            ldsm_x4(ql4, qaddr + AQL);
#pragma unroll
            for (int np = 0; np < 4; np++) {
                uint32_t krow = np * 16 + k_row4;
                uint32_t kaddr = kb + krow * 128 + (((2 * ks + k_kh) ^ axor) * 16);
                uint32_t kbh4[4], kbl4[4];
                ldsm_x4(kbh4, kaddr + SKH);
                ldsm_x4(kbl4, kaddr + SKL);
#pragma unroll
                for (int hf = 0; hf < 2; hf++)
                    mma_bf16(s[np * 2 + hf], qh4, &kbh4[hf * 2]);
#pragma unroll
                for (int hf = 0; hf < 2; hf++)
                    mma_bf16(s[np * 2 + hf], qh4, &kbl4[hf * 2]);
#pragma unroll
                for (int hf = 0; hf < 2; hf++)
                    mma_bf16(s[np * 2 + hf], ql4, &kbh4[hf * 2]);
            }
        }

        // ---- scale + causal mask + online softmax ----
        float mx0 = -1e30f, mx1 = -1e30f;
#pragma unroll
        for (int nf = 0; nf < 8; nf++) {
            int col = kt * 64 + nf * 8 + colb;
            float v0 = s[nf][0] * 0.125f;
            float v1 = s[nf][1] * 0.125f;
            float v2 = s[nf][2] * 0.125f;
            float v3 = s[nf][3] * 0.125f;
            if (col     > grow0)     v0 = -1e30f;
            if (col + 1 > grow0)     v1 = -1e30f;
            if (col     > grow0 + 8) v2 = -1e30f;
            if (col + 1 > grow0 + 8) v3 = -1e30f;
            s[nf][0] = v0; s[nf][1] = v1; s[nf][2] = v2; s[nf][3] = v3;
            mx0 = fmaxf(mx0, fmaxf(v0, v1));
            mx1 = fmaxf(mx1, fmaxf(v2, v3));
        }
        mx0 = fmaxf(mx0, __shfl_xor_sync(0xFFFFFFFFu, mx0, 1));
        mx0 = fmaxf(mx0, __shfl_xor_sync(0xFFFFFFFFu, mx0, 2));
        mx1 = fmaxf(mx1, __shfl_xor_sync(0xFFFFFFFFu, mx1, 1));
        mx1 = fmaxf(mx1, __shfl_xor_sync(0xFFFFFFFFu, mx1, 2));

        float mn0 = fmaxf(m0, mx0), mn1 = fmaxf(m1, mx1);
        float cr0 = __expf(m0 - mn0), cr1 = __expf(m1 - mn1);
        float rs0 = 0.0f, rs1 = 0.0f;
#pragma unroll
        for (int nf = 0; nf < 8; nf++) {
            s[nf][0] = __expf(s[nf][0] - mn0);
            s[nf][1] = __expf(s[nf][1] - mn0);
            s[nf][2] = __expf(s[nf][2] - mn1);
            s[nf][3] = __expf(s[nf][3] - mn1);
            rs0 += s[nf][0] + s[nf][1];
            rs1 += s[nf][2] + s[nf][3];
        }
        rs0 += __shfl_xor_sync(0xFFFFFFFFu, rs0, 1);
        rs0 += __shfl_xor_sync(0xFFFFFFFFu, rs0, 2);
        rs1 += __shfl_xor_sync(0xFFFFFFFFu, rs1, 1);
        rs1 += __shfl_xor_sync(0xFFFFFFFFu, rs1, 2);
        l0 = l0 * cr0 + rs0;
        l1 = l1 * cr1 + rs1;
        m0 = mn0; m1 = mn1;
#pragma unroll
        for (int nf = 0; nf < 8; nf++) {
            o[nf][0] *= cr0; o[nf][1] *= cr0;
            o[nf][2] *= cr1; o[nf][3] *= cr1;
        }

        // ---- O += P V (compensated, term-major) ----
#pragma unroll
        for (int ks = 0; ks < 4; ks++) {
            uint32_t pah[4], pal[4];
            float r0a, r0b, r1a, r1b;
            pah[0] = pack_bf16_res(s[2 * ks][0],     s[2 * ks][1],     r0a, r0b);
            pal[0] = pack_bf16(r0a, r0b);
            pah[1] = pack_bf16_res(s[2 * ks][2],     s[2 * ks][3],     r1a, r1b);
            pal[1] = pack_bf16(r1a, r1b);
            pah[2] = pack_bf16_res(s[2 * ks + 1][0], s[2 * ks + 1][1], r0a, r0b);
            pal[2] = pack_bf16(r0a, r0b);
            pah[3] = pack_bf16_res(s[2 * ks + 1][2], s[2 * ks + 1][3], r1a, r1b);
            pal[3] = pack_bf16(r1a, r1b);

            uint32_t vrow = ks * 16 + (lane & 15);
#pragma unroll
            for (int np = 0; np < 4; np++) {
                uint32_t vchunk = ((uint32_t)(2 * np) + (lane >> 4)) ^ axor;
                uint32_t vaddr = kb + vrow * 128 + (vchunk * 16);
                uint32_t vbh4[4], vbl4[4];
                ldsm_x4_t(vbh4, vaddr + SVH);
                ldsm_x4_t(vbl4, vaddr + SVL);
#pragma unroll
                for (int hf = 0; hf < 2; hf++)
                    mma_bf16(o[np * 2 + hf], pah, &vbh4[hf * 2]);
#pragma unroll
                for (int hf = 0; hf < 2; hf++)
                    mma_bf16(o[np * 2 + hf], pal, &vbh4[hf * 2]);
#pragma unroll
                for (int hf = 0; hf < 2; hf++)
                    mma_bf16(o[np * 2 + hf], pah, &vbl4[hf * 2]);
            }
        }
        __syncthreads();
    }

    // epilogue: normalize, split hi/lo, write bf16 ctx (A of the O-projection)
    const float il0 = 1.0f / l0, il1 = 1.0f / l1;
    size_t i0 = (mb + qbase + wq * 16 + (lane >> 2)) * (size_t)DMODEL + h * HD + colb;
    size_t i1 = i0 + 8 * DMODEL;
#pragma unroll
    for (int nf = 0; nf < 8; nf++) {
        float ra, rb;
        uint32_t h0 = pack_bf16_res(o[nf][0] * il0, o[nf][1] * il0, ra, rb);
        *(uint32_t*)(Ch + i0 + nf * 8) = h0;
        *(uint32_t*)(Cl + i0 + nf * 8) = pack_bf16(ra, rb);
        uint32_t h1 = pack_bf16_res(o[nf][2] * il1, o[nf][3] * il1, ra, rb);
        *(uint32_t*)(Ch + i1 + nf * 8) = h1;
        *(uint32_t*)(Cl + i1 + nf * 8) = pack_bf16(ra, rb);
    }
}

// ---------------------------------------------------------------------------
// Launch
// ---------------------------------------------------------------------------
extern "C" void kernel_launch(void* const* d_in, const int* in_sizes, int n_in,
                              void* d_out, int out_size) {
    const float* x     = (const float*)d_in[0];   // [4,2048,1024]
    const int*   pos   = (const int*)d_in[1];     // [2048]
    const float* qkv_w = (const float*)d_in[2];   // [3072,1024]
    const float* o_w   = (const float*)d_in[3];   // [1024,1024]
    float* out = (float*)d_out;                   // [4,2048,1024]

    __nv_bfloat16 *ah, *al, *bh, *bl, *oh, *ol, *qh, *ql;
    float2* rt;
    cudaGetSymbolAddress((void**)&ah, g_ah);
    cudaGetSymbolAddress((void**)&al, g_al);
    cudaGetSymbolAddress((void**)&bh, g_bh);
    cudaGetSymbolAddress((void**)&bl, g_bl);
    cudaGetSymbolAddress((void**)&oh, g_oh);
    cudaGetSymbolAddress((void**)&ol, g_ol);
    cudaGetSymbolAddress((void**)&qh, g_qh);
    cudaGetSymbolAddress((void**)&ql, g_ql);
    cudaGetSymbolAddress((void**)&rt, g_rope);

    cudaFuncSetAttribute(gemm_qkv, cudaFuncAttributeMaxDynamicSharedMemorySize, GEMM_SMEM);
    cudaFuncSetAttribute(gemm_mma, cudaFuncAttributeMaxDynamicSharedMemorySize, GEMM_SMEM);
    cudaFuncSetAttribute(attn_mma, cudaFuncAttributeMaxDynamicSharedMemorySize, ATT_SMEM);

    // 1) fused prep: split x, qkv_w, o_w; rope table (one launch)
    {
        int total = NX4 + NW4 + NO4 + S_LEN * 32;
        prep_all<<<(total + 255) / 256, 256>>>(x, qkv_w, o_w, pos,
                                               ah, al, bh, bl, oh, ol, rt);
    }
    // 2) QKV projection + fused RoPE + bf16 split-out
    {
        dim3 grid(N3 / 128, MROWS / 128);
        gemm_qkv<<<grid, 256, GEMM_SMEM>>>(ah, al, bh, bl, qh, ql, rt);
    }
    // 3) flash attention -> ctx bf16 hi/lo (into ah/al)
    {
        dim3 grid(S_LEN / 128, BATCH * NH);
        attn_mma<<<grid, 256, ATT_SMEM>>>(qh, ql, ah, al);
    }
    // 4) output projection -> fp32 out
    {
        dim3 grid(DMODEL / 128, MROWS / 128);
        gemm_mma<<<grid, 256, GEMM_SMEM>>>(ah, al, oh, ol, out, DMODEL, DMODEL);
    }
}

// round 17
// speedup vs baseline: 3.4697x; 1.2276x over previous
#include <cuda_runtime.h>
#include <cuda_bf16.h>
#include <cuda_fp16.h>
#include <math.h>
#include <stdint.h>

// Problem constants
#define S_LEN  2048
#define DMODEL 1024
#define NH     16
#define HD     64
#define BATCH  4
#define MROWS  (BATCH * S_LEN)   // 8192
#define N3     (3 * DMODEL)      // 3072

// Scratch (device globals; no allocation allowed)
__device__ __half g_xh[(size_t)MROWS * DMODEL];         // x hi (fp16), then ctx hi
__device__ __half g_bh[(size_t)N3 * DMODEL];            // qkv_w hi (fp16)
__device__ __half g_bl[(size_t)N3 * DMODEL];            // qkv_w lo (fp16)
__device__ __half g_oh[(size_t)DMODEL * DMODEL];        // o_w hi
__device__ __half g_ol[(size_t)DMODEL * DMODEL];        // o_w lo
__device__ __nv_bfloat16 g_qh[(size_t)MROWS * N3];      // qkv hi bf16 (rope applied)
__device__ __nv_bfloat16 g_ql[(size_t)MROWS * N3];      // qkv lo bf16
__device__ float2 g_rope[S_LEN * (HD / 2)];             // (cos, sin) packed

// ---------------------------------------------------------------------------
// PTX helpers (portable sm_80+ only)
// ---------------------------------------------------------------------------
__device__ __forceinline__ uint32_t smem_u32(const void* p) {
    uint32_t a;
    asm("{ .reg .u64 t; cvta.to.shared.u64 t, %1; cvt.u32.u64 %0, t; }" : "=r"(a) : "l"(p));
    return a;
}
__device__ __forceinline__ void cp_async16(uint32_t saddr, const void* gaddr) {
    asm volatile("cp.async.cg.shared.global [%0], [%1], 16;" :: "r"(saddr), "l"(gaddr));
}
__device__ __forceinline__ void ldsm_x4(uint32_t* r, uint32_t addr) {
    asm volatile("ldmatrix.sync.aligned.m8n8.x4.shared.b16 {%0,%1,%2,%3}, [%4];"
                 : "=r"(r[0]), "=r"(r[1]), "=r"(r[2]), "=r"(r[3]) : "r"(addr));
}
__device__ __forceinline__ void ldsm_x4_t(uint32_t* r, uint32_t addr) {
    asm volatile("ldmatrix.sync.aligned.m8n8.x4.trans.shared.b16 {%0,%1,%2,%3}, [%4];"
                 : "=r"(r[0]), "=r"(r[1]), "=r"(r[2]), "=r"(r[3]) : "r"(addr));
}
__device__ __forceinline__ void mma_bf16(float* c, const uint32_t* a, const uint32_t* b) {
    asm volatile(
        "mma.sync.aligned.m16n8k16.row.col.f32.bf16.bf16.f32 "
        "{%0,%1,%2,%3}, {%4,%5,%6,%7}, {%8,%9}, {%0,%1,%2,%3};"
        : "+f"(c[0]), "+f"(c[1]), "+f"(c[2]), "+f"(c[3])
        : "r"(a[0]), "r"(a[1]), "r"(a[2]), "r"(a[3]), "r"(b[0]), "r"(b[1]));
}
__device__ __forceinline__ void mma_f16(float* c, const uint32_t* a, const uint32_t* b) {
    asm volatile(
        "mma.sync.aligned.m16n8k16.row.col.f32.f16.f16.f32 "
        "{%0,%1,%2,%3}, {%4,%5,%6,%7}, {%8,%9}, {%0,%1,%2,%3};"
        : "+f"(c[0]), "+f"(c[1]), "+f"(c[2]), "+f"(c[3])
        : "r"(a[0]), "r"(a[1]), "r"(a[2]), "r"(a[3]), "r"(b[0]), "r"(b[1]));
}
__device__ __forceinline__ uint32_t pack_bf16_res(float lo, float hi, float& rlo, float& rhi) {
    __nv_bfloat16 a = __float2bfloat16(lo), b = __float2bfloat16(hi);
    rlo = lo - __bfloat162float(a);
    rhi = hi - __bfloat162float(b);
    return (uint32_t)__bfloat16_as_ushort(a) | ((uint32_t)__bfloat16_as_ushort(b) << 16);
}
__device__ __forceinline__ uint32_t pack_bf16(float lo, float hi) {
    __nv_bfloat16 a = __float2bfloat16(lo), b = __float2bfloat16(hi);
    return (uint32_t)__bfloat16_as_ushort(a) | ((uint32_t)__bfloat16_as_ushort(b) << 16);
}
__device__ __forceinline__ uint32_t pack_h2(float a, float b) {
    __half x = __float2half_rn(a), y = __float2half_rn(b);
    return (uint32_t)__half_as_ushort(x) | ((uint32_t)__half_as_ushort(y) << 16);
}

// ---------------------------------------------------------------------------
// Fused prep: x -> fp16 hi; qkv_w, o_w -> fp16 hi/lo; rope table. One launch.
// ---------------------------------------------------------------------------
#define NX4 (MROWS * DMODEL / 4)        // 2097152
#define NW4 (N3 * DMODEL / 4)           // 786432
#define NO4 (DMODEL * DMODEL / 4)       // 262144

__device__ __forceinline__ void split4_h(const float* __restrict__ in,
                                         __half* __restrict__ hi,
                                         __half* __restrict__ lo, int i) {
    float4 v = ((const float4*)in)[i];
    __half hx = __float2half_rn(v.x), hy = __float2half_rn(v.y);
    __half hz = __float2half_rn(v.z), hw = __float2half_rn(v.w);
    __half lx = __float2half_rn(v.x - __half2float(hx));
    __half ly = __float2half_rn(v.y - __half2float(hy));
    __half lz = __float2half_rn(v.z - __half2float(hz));
    __half lw = __float2half_rn(v.w - __half2float(hw));
    ((__half2*)hi)[i * 2]     = __halves2half2(hx, hy);
    ((__half2*)hi)[i * 2 + 1] = __halves2half2(hz, hw);
    ((__half2*)lo)[i * 2]     = __halves2half2(lx, ly);
    ((__half2*)lo)[i * 2 + 1] = __halves2half2(lz, lw);
}

__global__ void prep_all(const float* __restrict__ x,
                         const float* __restrict__ qkv_w,
                         const float* __restrict__ o_w,
                         const int* __restrict__ pos,
                         __half* __restrict__ xh,
                         __half* __restrict__ bh, __half* __restrict__ bl,
                         __half* __restrict__ oh, __half* __restrict__ ol,
                         float2* __restrict__ rtab) {
    int i = blockIdx.x * blockDim.x + threadIdx.x;
    if (i < NX4) {
        float4 v = ((const float4*)x)[i];
        ((__half2*)xh)[i * 2]     = __halves2half2(__float2half_rn(v.x), __float2half_rn(v.y));
        ((__half2*)xh)[i * 2 + 1] = __halves2half2(__float2half_rn(v.z), __float2half_rn(v.w));
    } else if (i < NX4 + NW4) {
        split4_h(qkv_w, bh, bl, i - NX4);
    } else if (i < NX4 + NW4 + NO4) {
        split4_h(o_w, oh, ol, i - NX4 - NW4);
    } else {
        int j = i - NX4 - NW4 - NO4;
        if (j < S_LEN * 32) {
            int s = j >> 5, k = j & 31;
            float freq = powf(10000.0f, (float)k * (1.0f / 32.0f));
            float ang = (float)pos[s] * (1.0f / freq);
            float sn, cs;
            sincosf(ang, &sn, &cs);
            rtab[j] = make_float2(cs, sn);
        }
    }
}

// ---------------------------------------------------------------------------
// fp16 2-term GEMM mainloop: C += Ah*(Bh+Bl). Swizzled smem, 3-stage
// cp.async pipeline (round-12 schedule). 128x128 CTA tile, 256 thr, K-chunk 32.
// smem per stage: AH(8K) BH(8K) BL(8K) = 24KB.
// ---------------------------------------------------------------------------
#define STAGE_BYTES 24576
#define GEMM_SMEM   (3 * STAGE_BYTES)
#define OFF_AH 0
#define OFF_BH 8192
#define OFF_BL 16384

__device__ __forceinline__ void load_stage(uint32_t sbase,
                                           const __half* Ah,
                                           const __half* Bh, const __half* Bl,
                                           int K, int bm, int bn, int k0, int tid) {
#pragma unroll
    for (int i = 0; i < 2; i++) {
        int c = tid * 2 + i;
        int row = c >> 2;
        int cc = c & 3;
        uint32_t so = row * 64 + ((cc ^ ((row >> 1) & 3)) * 16);
        size_t goA = (size_t)(bm + row) * K + k0 + cc * 8;
        size_t goB = (size_t)(bn + row) * K + k0 + cc * 8;
        cp_async16(sbase + OFF_AH + so, Ah + goA);
        cp_async16(sbase + OFF_BH + so, Bh + goB);
        cp_async16(sbase + OFF_BL + so, Bl + goB);
    }
}

__device__ __forceinline__ void gemm_mainloop(uint32_t sb,
                                              const __half* Ah,
                                              const __half* Bh, const __half* Bl,
                                              int Kdim, int bm, int bn, int tid,
                                              float acc[4][4][4]) {
    const int wid = tid >> 5, lane = tid & 31;
    const int wm = wid >> 2, wn = wid & 3;
    const int a_row_base = wm * 64 + (lane & 15);
    const uint32_t axg = ((lane & 15) >> 1) & 3;
    const uint32_t a_csel = lane >> 4;
    const int b_row4 = wn * 32 + ((lane >> 4) & 1) * 8 + (lane & 7);
    const uint32_t b_kh = (lane >> 3) & 1;

    const int nch = Kdim >> 5;
    load_stage(sb, Ah, Bh, Bl, Kdim, bm, bn, 0, tid);
    asm volatile("cp.async.commit_group;");
    if (nch > 1) {
        load_stage(sb + STAGE_BYTES, Ah, Bh, Bl, Kdim, bm, bn, 32, tid);
        asm volatile("cp.async.commit_group;");
    }

    int cur = 0, pre = 2;
    for (int c = 0; c < nch; c++) {
        if (c + 2 < nch) {
            load_stage(sb + pre * STAGE_BYTES, Ah, Bh, Bl,
                       Kdim, bm, bn, (c + 2) * 32, tid);
            asm volatile("cp.async.commit_group;");
            pre = (pre == 2) ? 0 : pre + 1;
            asm volatile("cp.async.wait_group 2;");
        } else if (c + 1 < nch) {
            asm volatile("cp.async.wait_group 1;");
        } else {
            asm volatile("cp.async.wait_group 0;");
        }
        __syncthreads();

        const uint32_t st = sb + cur * STAGE_BYTES;
#pragma unroll
        for (int ks = 0; ks < 2; ks++) {
            uint32_t bh4[2][4], bl4[2][4];
#pragma unroll
            for (int np = 0; np < 2; np++) {
                int brow = b_row4 + np * 16;
                uint32_t bxg = ((uint32_t)brow >> 1) & 3;
                uint32_t baddr = st + brow * 64 + (((ks * 2 + b_kh) ^ bxg) * 16);
                ldsm_x4(bh4[np], baddr + OFF_BH);
                ldsm_x4(bl4[np], baddr + OFF_BL);
            }
#pragma unroll
            for (int mf = 0; mf < 4; mf++) {
                uint32_t aaddr = st + (a_row_base + mf * 16) * 64 +
                                 (((ks * 2 + a_csel) ^ axg) * 16);
                uint32_t ah[4];
                ldsm_x4(ah, aaddr + OFF_AH);
#pragma unroll
                for (int np = 0; np < 2; np++)
#pragma unroll
                    for (int hf = 0; hf < 2; hf++)
                        mma_f16(acc[mf][np * 2 + hf], ah, &bh4[np][hf * 2]);
#pragma unroll
                for (int np = 0; np < 2; np++)
#pragma unroll
                    for (int hf = 0; hf < 2; hf++)
                        mma_f16(acc[mf][np * 2 + hf], ah, &bl4[np][hf * 2]);
            }
        }
        cur = (cur == 2) ? 0 : cur + 1;
        __syncthreads();
    }
}

// ---------------------------------------------------------------------------
// QKV GEMM with fused RoPE + bf16 hi/lo output (attention consumes bf16).
// ---------------------------------------------------------------------------
__global__ __launch_bounds__(256, 2) void gemm_qkv(const __half* __restrict__ Ah,
                                                   const __half* __restrict__ Bh,
                                                   const __half* __restrict__ Bl,
                                                   __nv_bfloat16* __restrict__ Qh,
                                                   __nv_bfloat16* __restrict__ Ql,
                                                   const float2* __restrict__ rtab) {
    extern __shared__ char smem[];
    const uint32_t sb = smem_u32(smem);
    const int tid = threadIdx.x;
    const int wid = tid >> 5, lane = tid & 31;
    const int bm = blockIdx.y * 128, bn = blockIdx.x * 128;

    float acc[4][4][4];
#pragma unroll
    for (int a = 0; a < 4; a++)
#pragma unroll
        for (int b = 0; b < 4; b++)
#pragma unroll
            for (int r = 0; r < 4; r++) acc[a][b][r] = 0.0f;

    gemm_mainloop(sb, Ah, Bh, Bl, DMODEL, bm, bn, tid, acc);

    const int r0 = bm + (wid >> 2) * 64 + (lane >> 2);
    const int c0 = bn + (wid & 3) * 32 + (lane & 3) * 2;
#pragma unroll
    for (int mf = 0; mf < 4; mf++) {
        const int row = r0 + mf * 16;
        const int s0 = row & (S_LEN - 1);
        const int s1 = (row + 8) & (S_LEN - 1);
#pragma unroll
        for (int nf = 0; nf < 4; nf++) {
            const int col = c0 + nf * 8;
            float v0 = acc[mf][nf][0], v1 = acc[mf][nf][1];
            float v2 = acc[mf][nf][2], v3 = acc[mf][nf][3];
            if (col < 2 * DMODEL) {  // q or k: rotate
                const int j = (col & 63) >> 1;
                float2 t0v = rtab[s0 * 32 + j];
                float2 t1v = rtab[s1 * 32 + j];
                float t0 = v0 * t0v.x - v1 * t0v.y;
                v1 = v0 * t0v.y + v1 * t0v.x; v0 = t0;
                float t2 = v2 * t1v.x - v3 * t1v.y;
                v3 = v2 * t1v.y + v3 * t1v.x; v2 = t2;
            }
            float ra, rb;
            size_t i0 = (size_t)row * N3 + col;
            size_t i1 = (size_t)(row + 8) * N3 + col;
            uint32_t h0 = pack_bf16_res(v0, v1, ra, rb);
            *(uint32_t*)(Qh + i0) = h0;
            *(uint32_t*)(Ql + i0) = pack_bf16(ra, rb);
            uint32_t h1 = pack_bf16_res(v2, v3, ra, rb);
            *(uint32_t*)(Qh + i1) = h1;
            *(uint32_t*)(Ql + i1) = pack_bf16(ra, rb);
        }
    }
}

// ---------------------------------------------------------------------------
// O-projection GEMM: fp32 out.
// ---------------------------------------------------------------------------
__global__ __launch_bounds__(256, 2) void gemm_mma(const __half* __restrict__ Ah,
                                                   const __half* __restrict__ Bh,
                                                   const __half* __restrict__ Bl,
                                                   float* __restrict__ C,
                                                   int Ndim, int Kdim) {
    extern __shared__ char smem[];
    const uint32_t sb = smem_u32(smem);
    const int tid = threadIdx.x;
    const int wid = tid >> 5, lane = tid & 31;
    const int bm = blockIdx.y * 128, bn = blockIdx.x * 128;

    float acc[4][4][4];
#pragma unroll
    for (int a = 0; a < 4; a++)
#pragma unroll
        for (int b = 0; b < 4; b++)
#pragma unroll
            for (int r = 0; r < 4; r++) acc[a][b][r] = 0.0f;

    gemm_mainloop(sb, Ah, Bh, Bl, Kdim, bm, bn, tid, acc);

    const int r0 = bm + (wid >> 2) * 64 + (lane >> 2);
    const int c0 = bn + (wid & 3) * 32 + (lane & 3) * 2;
#pragma unroll
    for (int mf = 0; mf < 4; mf++) {
#pragma unroll
        for (int nf = 0; nf < 4; nf++) {
            float* p0 = C + (size_t)(r0 + mf * 16) * Ndim + c0 + nf * 8;
            float* p1 = p0 + 8 * Ndim;
            *(float2*)p0 = make_float2(acc[mf][nf][0], acc[mf][nf][1]);
            *(float2*)p1 = make_float2(acc[mf][nf][2], acc[mf][nf][3]);
        }
    }
}

// ---------------------------------------------------------------------------
// Flash attention (mma.sync, bf16 3-term — proven). CTA: 128 queries,
// 8 warps x 16 rows, KTILE 64, double-buffered K/V.
// Epilogue writes ctx as fp16 hi only (feeds the fp16 O-projection).
// smem 96KB: Q (32K) + 2 stages x (KH KL VH VL, 8K each).
// ---------------------------------------------------------------------------
#define AQH 0
#define AQL 16384
#define KVBASE 32768
#define KV_STAGE 32768
#define SKH 0
#define SKL 8192
#define SVH 16384
#define SVL 24576
#define ATT_SMEM 98304

__device__ __forceinline__ void attn_load_kv(uint32_t sbK, const __nv_bfloat16* Qh,
                                             const __nv_bfloat16* Ql, size_t mb,
                                             int kt, int koff, int voff, int tid) {
#pragma unroll
    for (int i = 0; i < 2; i++) {
        int c = tid + 256 * i;
        int row = c >> 3, j = c & 7;
        uint32_t dst = sbK + (uint32_t)(row * 128 + ((j ^ (row & 7)) * 16));
        size_t g = (mb + kt * 64 + row) * (size_t)N3 + j * 8;
        cp_async16(dst + SKH, Qh + g + koff);
        cp_async16(dst + SKL, Ql + g + koff);
        cp_async16(dst + SVH, Qh + g + voff);
        cp_async16(dst + SVL, Ql + g + voff);
    }
}

__global__ __launch_bounds__(256, 2) void attn_mma(const __nv_bfloat16* __restrict__ Qh,
                                                   const __nv_bfloat16* __restrict__ Ql,
                                                   __half* __restrict__ Cx) {
    extern __shared__ char smem[];
    const uint32_t sb = smem_u32(smem);
    const int qt = (S_LEN / 128 - 1) - blockIdx.x;   // big CTAs first
    const int bh = blockIdx.y;
    const int b = bh >> 4, h = bh & 15;
    const int tid = threadIdx.x;
    const int wq = tid >> 5, lane = tid & 31;
    const size_t mb = (size_t)b * S_LEN;
    const int qbase = qt * 128;
    const int qoff = h * HD;
    const int koff = DMODEL + h * HD;
    const int voff = 2 * DMODEL + h * HD;
    const uint32_t axor = (uint32_t)(lane & 7);

    // stage Q tile (128 rows x 64 cols, hi+lo)
#pragma unroll
    for (int i = 0; i < 4; i++) {
        int c = tid + 256 * i;
        int row = c >> 3, j = c & 7;
        uint32_t dst = sb + (uint32_t)(row * 128 + ((j ^ (row & 7)) * 16));
        size_t g = (mb + qbase + row) * (size_t)N3 + qoff + j * 8;
        cp_async16(dst + AQH, Qh + g);
        cp_async16(dst + AQL, Ql + g);
    }
    asm volatile("cp.async.commit_group;");
    // prefetch K/V tile 0
    attn_load_kv(sb + KVBASE, Qh, Ql, mb, 0, koff, voff, tid);
    asm volatile("cp.async.commit_group;");

    float o[8][4];
#pragma unroll
    for (int nf = 0; nf < 8; nf++)
#pragma unroll
        for (int r = 0; r < 4; r++) o[nf][r] = 0.0f;
    float m0 = -1e30f, m1 = -1e30f, l0 = 0.0f, l1 = 0.0f;

    const uint32_t qrow = wq * 16 + (lane & 15);
    const int grow0 = qbase + wq * 16 + (lane >> 2);
    const int colb = (lane & 3) * 2;
    const uint32_t k_row4 = ((lane >> 4) & 1) * 8 + (lane & 7);
    const uint32_t k_kh = (lane >> 3) & 1;

    const int nkt = 2 * (qt + 1);
    for (int kt = 0; kt < nkt; kt++) {
        if (kt + 1 < nkt) {
            attn_load_kv(sb + KVBASE + ((kt + 1) & 1) * KV_STAGE,
                         Qh, Ql, mb, kt + 1, koff, voff, tid);
            asm volatile("cp.async.commit_group;");
            asm volatile("cp.async.wait_group 1;");
        } else {
            asm volatile("cp.async.wait_group 0;");
        }
        __syncthreads();
        const uint32_t kb = sb + KVBASE + (kt & 1) * KV_STAGE;

        // ---- S = Q K^T (compensated, term-major) ----
        float s[8][4];
#pragma unroll
        for (int nf = 0; nf < 8; nf++)
#pragma unroll
            for (int r = 0; r < 4; r++) s[nf][r] = 0.0f;

#pragma unroll
        for (int ks = 0; ks < 4; ks++) {
            uint32_t qaddr = sb + qrow * 128 + (((2 * ks + (lane >> 4)) ^ axor) * 16);
            uint32_t qh4[4], ql4[4];
            ldsm_x4(qh4, qaddr + AQH);
            ldsm_x4(ql4, qaddr + AQL);
#pragma unroll
            for (int np = 0; np < 4; np++) {
                uint32_t krow = np * 16 + k_row4;
                uint32_t kaddr = kb + krow * 128 + (((2 * ks + k_kh) ^ axor) * 16);
                uint32_t kbh4[4], kbl4[4];
                ldsm_x4(kbh4, kaddr + SKH);
                ldsm_x4(kbl4, kaddr + SKL);
#pragma unroll
                for (int hf = 0; hf < 2; hf++)
                    mma_bf16(s[np * 2 + hf], qh4, &kbh4[hf * 2]);
#pragma unroll
                for (int hf = 0; hf < 2; hf++)
                    mma_bf16(s[np * 2 + hf], qh4, &kbl4[hf * 2]);
#pragma unroll
                for (int hf = 0; hf < 2; hf++)
                    mma_bf16(s[np * 2 + hf], ql4, &kbh4[hf * 2]);
            }
        }

        // ---- scale + causal mask + online softmax ----
        float mx0 = -1e30f, mx1 = -1e30f;
#pragma unroll
        for (int nf = 0; nf < 8; nf++) {
            int col = kt * 64 + nf * 8 + colb;
            float v0 = s[nf][0] * 0.125f;
            float v1 = s[nf][1] * 0.125f;
            float v2 = s[nf][2] * 0.125f;
            float v3 = s[nf][3] * 0.125f;
            if (col     > grow0)     v0 = -1e30f;
            if (col + 1 > grow0)     v1 = -1e30f;
            if (col     > grow0 + 8) v2 = -1e30f;
            if (col + 1 > grow0 + 8) v3 = -1e30f;
            s[nf][0] = v0; s[nf][1] = v1; s[nf][2] = v2; s[nf][3] = v3;
            mx0 = fmaxf(mx0, fmaxf(v0, v1));
            mx1 = fmaxf(mx1, fmaxf(v2, v3));
        }
        mx0 = fmaxf(mx0, __shfl_xor_sync(0xFFFFFFFFu, mx0, 1));
        mx0 = fmaxf(mx0, __shfl_xor_sync(0xFFFFFFFFu, mx0, 2));
        mx1 = fmaxf(mx1, __shfl_xor_sync(0xFFFFFFFFu, mx1, 1));
        mx1 = fmaxf(mx1, __shfl_xor_sync(0xFFFFFFFFu, mx1, 2));

        float mn0 = fmaxf(m0, mx0), mn1 = fmaxf(m1, mx1);
        float cr0 = __expf(m0 - mn0), cr1 = __expf(m1 - mn1);
        float rs0 = 0.0f, rs1 = 0.0f;
#pragma unroll
        for (int nf = 0; nf < 8; nf++) {
            s[nf][0] = __expf(s[nf][0] - mn0);
            s[nf][1] = __expf(s[nf][1] - mn0);
            s[nf][2] = __expf(s[nf][2] - mn1);
            s[nf][3] = __expf(s[nf][3] - mn1);
            rs0 += s[nf][0] + s[nf][1];
            rs1 += s[nf][2] + s[nf][3];
        }
        rs0 += __shfl_xor_sync(0xFFFFFFFFu, rs0, 1);
        rs0 += __shfl_xor_sync(0xFFFFFFFFu, rs0, 2);
        rs1 += __shfl_xor_sync(0xFFFFFFFFu, rs1, 1);
        rs1 += __shfl_xor_sync(0xFFFFFFFFu, rs1, 2);
        l0 = l0 * cr0 + rs0;
        l1 = l1 * cr1 + rs1;
        m0 = mn0; m1 = mn1;
#pragma unroll
        for (int nf = 0; nf < 8; nf++) {
            o[nf][0] *= cr0; o[nf][1] *= cr0;
            o[nf][2] *= cr1; o[nf][3] *= cr1;
        }

        // ---- O += P V (compensated, term-major) ----
#pragma unroll
        for (int ks = 0; ks < 4; ks++) {
            uint32_t pah[4], pal[4];
            float r0a, r0b, r1a, r1b;
            pah[0] = pack_bf16_res(s[2 * ks][0],     s[2 * ks][1],     r0a, r0b);
            pal[0] = pack_bf16(r0a, r0b);
            pah[1] = pack_bf16_res(s[2 * ks][2],     s[2 * ks][3],     r1a, r1b);
            pal[1] = pack_bf16(r1a, r1b);
            pah[2] = pack_bf16_res(s[2 * ks + 1][0], s[2 * ks + 1][1], r0a, r0b);
            pal[2] = pack_bf16(r0a, r0b);
            pah[3] = pack_bf16_res(s[2 * ks + 1][2], s[2 * ks + 1][3], r1a, r1b);
            pal[3] = pack_bf16(r1a, r1b);

            uint32_t vrow = ks * 16 + (lane & 15);
#pragma unroll
            for (int np = 0; np < 4; np++) {
                uint32_t vchunk = ((uint32_t)(2 * np) + (lane >> 4)) ^ axor;
                uint32_t vaddr = kb + vrow * 128 + (vchunk * 16);
                uint32_t vbh4[4], vbl4[4];
                ldsm_x4_t(vbh4, vaddr + SVH);
                ldsm_x4_t(vbl4, vaddr + SVL);
#pragma unroll
                for (int hf = 0; hf < 2; hf++)
                    mma_bf16(o[np * 2 + hf], pah, &vbh4[hf * 2]);
#pragma unroll
                for (int hf = 0; hf < 2; hf++)
                    mma_bf16(o[np * 2 + hf], pal, &vbh4[hf * 2]);
#pragma unroll
                for (int hf = 0; hf < 2; hf++)
                    mma_bf16(o[np * 2 + hf], pah, &vbl4[hf * 2]);
            }
        }
        __syncthreads();
    }

    // epilogue: normalize, write ctx as fp16 hi (A of the fp16 O-projection)
    const float il0 = 1.0f / l0, il1 = 1.0f / l1;
    size_t i0 = (mb + qbase + wq * 16 + (lane >> 2)) * (size_t)DMODEL + h * HD + colb;
    size_t i1 = i0 + 8 * DMODEL;
#pragma unroll
    for (int nf = 0; nf < 8; nf++) {
        *(uint32_t*)(Cx + i0 + nf * 8) = pack_h2(o[nf][0] * il0, o[nf][1] * il0);
        *(uint32_t*)(Cx + i1 + nf * 8) = pack_h2(o[nf][2] * il1, o[nf][3] * il1);
    }
}

// ---------------------------------------------------------------------------
// Launch
// ---------------------------------------------------------------------------
extern "C" void kernel_launch(void* const* d_in, const int* in_sizes, int n_in,
                              void* d_out, int out_size) {
    const float* x     = (const float*)d_in[0];   // [4,2048,1024]
    const int*   pos   = (const int*)d_in[1];     // [2048]
    const float* qkv_w = (const float*)d_in[2];   // [3072,1024]
    const float* o_w   = (const float*)d_in[3];   // [1024,1024]
    float* out = (float*)d_out;                   // [4,2048,1024]

    __half *xh, *bh, *bl, *oh, *ol;
    __nv_bfloat16 *qh, *ql;
    float2* rt;
    cudaGetSymbolAddress((void**)&xh, g_xh);
    cudaGetSymbolAddress((void**)&bh, g_bh);
    cudaGetSymbolAddress((void**)&bl, g_bl);
    cudaGetSymbolAddress((void**)&oh, g_oh);
    cudaGetSymbolAddress((void**)&ol, g_ol);
    cudaGetSymbolAddress((void**)&qh, g_qh);
    cudaGetSymbolAddress((void**)&ql, g_ql);
    cudaGetSymbolAddress((void**)&rt, g_rope);

    cudaFuncSetAttribute(gemm_qkv, cudaFuncAttributeMaxDynamicSharedMemorySize, GEMM_SMEM);
    cudaFuncSetAttribute(gemm_mma, cudaFuncAttributeMaxDynamicSharedMemorySize, GEMM_SMEM);
    cudaFuncSetAttribute(attn_mma, cudaFuncAttributeMaxDynamicSharedMemorySize, ATT_SMEM);

    // 1) fused prep: x -> fp16 hi; qkv_w, o_w -> fp16 hi/lo; rope table
    {
        int total = NX4 + NW4 + NO4 + S_LEN * 32;
        prep_all<<<(total + 255) / 256, 256>>>(x, qkv_w, o_w, pos,
                                               xh, bh, bl, oh, ol, rt);
    }
    // 2) QKV projection (fp16 2-term) + fused RoPE + bf16 split-out
    {
        dim3 grid(N3 / 128, MROWS / 128);
        gemm_qkv<<<grid, 256, GEMM_SMEM>>>(xh, bh, bl, qh, ql, rt);
    }
    // 3) flash attention (bf16 3-term) -> ctx fp16 hi (into xh)
    {
        dim3 grid(S_LEN / 128, BATCH * NH);
        attn_mma<<<grid, 256, ATT_SMEM>>>(qh, ql, xh);
    }
    // 4) output projection (fp16 2-term) -> fp32 out
    {
        dim3 grid(DMODEL / 128, MROWS / 128);
        gemm_mma<<<grid, 256, GEMM_SMEM>>>(xh, oh, ol, out, DMODEL, DMODEL);
    }
}